// round 8
// baseline (speedup 1.0000x reference)
#include <cuda_runtime.h>
#include <cstdint>

#define NN   100000
#define EE   1600000
#define KDIM 256

// ---------------- scratch (device globals) ----------------
__device__ unsigned g_ph[(size_t)NN * 128];  // split A (x, later z)  [row][kpair]
__device__ unsigned g_pl[(size_t)NN * 128];
__device__ unsigned g_rh[(size_t)NN * 128];  // split h0
__device__ unsigned g_rl[(size_t)NN * 128];
__device__ float    g_t [(size_t)NN * KDIM]; // t = h0 @ We
__device__ float    g_h1[(size_t)NN * KDIM]; // h1
// weights pre-split, transposed to [n][kpair]
__device__ unsigned g_wdh[256 * 128], g_wdl[256 * 128];
__device__ unsigned g_weh[256 * 128], g_wel[256 * 128];
__device__ unsigned g_wch[256 * 128], g_wcl[256 * 128];
__device__ float    g_bcat[256];
__device__ float g_deg[NN];
__device__ float g_dinv[NN];
__device__ int   g_cnt[NN];
__device__ int   g_rowptr[NN + 1];
__device__ int   g_cursor[NN];
__device__ int   g_src[EE];
__device__ float g_val[EE];
__device__ int   g_is64;

// ---------------- helpers ----------------
__device__ __forceinline__ void split_pair(float x0, float x1,
                                           unsigned& hi, unsigned& lo) {
    unsigned h;
    asm("cvt.rn.bf16x2.f32 %0, %1, %2;" : "=r"(h) : "f"(x1), "f"(x0));
    float h0 = __uint_as_float(h << 16);
    float h1 = __uint_as_float(h & 0xffff0000u);
    float r0 = x0 - h0, r1 = x1 - h1;
    unsigned l;
    asm("cvt.rn.bf16x2.f32 %0, %1, %2;" : "=r"(l) : "f"(r1), "f"(r0));
    hi = h; lo = l;
}

__device__ __forceinline__ uint32_t smem_u32(const void* p) {
    uint32_t a;
    asm("{ .reg .u64 t; cvta.to.shared.u64 t, %1; cvt.u32.u64 %0, t; }"
        : "=r"(a) : "l"(p));
    return a;
}

__device__ __forceinline__ void ldsm_x4(unsigned r[4], uint32_t addr) {
    asm volatile("ldmatrix.sync.aligned.m8n8.x4.shared.b16 {%0,%1,%2,%3}, [%4];"
        : "=r"(r[0]), "=r"(r[1]), "=r"(r[2]), "=r"(r[3]) : "r"(addr));
}

__device__ __forceinline__ void mma16(float c[4], const unsigned a[4],
                                      unsigned b0, unsigned b1) {
    asm volatile(
        "mma.sync.aligned.m16n8k16.row.col.f32.bf16.bf16.f32 "
        "{%0,%1,%2,%3}, {%4,%5,%6,%7}, {%8,%9}, {%0,%1,%2,%3};"
        : "+f"(c[0]), "+f"(c[1]), "+f"(c[2]), "+f"(c[3])
        : "r"(a[0]), "r"(a[1]), "r"(a[2]), "r"(a[3]), "r"(b0), "r"(b1));
}

// ---------------- edge-index dtype detection ----------------
__global__ void detect_kernel(const int* __restrict__ ei32, int n_int32) {
    __shared__ int any;
    if (threadIdx.x == 0) any = 0;
    __syncthreads();
    for (int i = threadIdx.x; i < 4096; i += blockDim.x) {
        int pos = 2 * i + 1;
        if (pos < n_int32 && ei32[pos] != 0) any = 1;
    }
    __syncthreads();
    if (threadIdx.x == 0) g_is64 = (any == 0) ? 1 : 0;
}

__device__ __forceinline__ int load_idx(const void* ei, int e, int part, int i) {
    if (g_is64) return (int)((const long long*)ei)[(size_t)part * e + i];
    return ((const int*)ei)[(size_t)part * e + i];
}

// ---------------- graph preprocessing ----------------
__global__ void init_kernel(int n) {
    int i = blockIdx.x * blockDim.x + threadIdx.x;
    if (i < n) { g_deg[i] = 1.0f; g_cnt[i] = 0; }
}

__global__ void edge_pass(const void* __restrict__ ei,
                          const float* __restrict__ ew, int e) {
    int i = blockIdx.x * blockDim.x + threadIdx.x;
    if (i >= e) return;
    int c = load_idx(ei, e, 1, i);
    if ((unsigned)c >= NN) return;
    atomicAdd(&g_deg[c], ew[i]);
    atomicAdd(&g_cnt[c], 1);
}

__global__ void dinv_kernel(int n) {
    int i = blockIdx.x * blockDim.x + threadIdx.x;
    if (i < n) g_dinv[i] = rsqrtf(g_deg[i]);
}

__global__ void scan_kernel(int n) {
    __shared__ int part[1024];
    int tid = threadIdx.x;
    int chunk = (n + 1023) >> 10;
    int beg = tid * chunk;
    int end = beg + chunk; if (end > n) end = n;
    int s = 0;
    for (int i = beg; i < end; i++) s += g_cnt[i];
    part[tid] = s;
    __syncthreads();
    for (int off = 1; off < 1024; off <<= 1) {
        int v = (tid >= off) ? part[tid - off] : 0;
        __syncthreads();
        part[tid] += v;
        __syncthreads();
    }
    int run = (tid > 0) ? part[tid - 1] : 0;
    for (int i = beg; i < end; i++) {
        g_rowptr[i] = run; g_cursor[i] = run; run += g_cnt[i];
    }
    if (tid == 1023) g_rowptr[n] = part[1023];
}

__global__ void scatter_kernel(const void* __restrict__ ei,
                               const float* __restrict__ ew, int e) {
    int i = blockIdx.x * blockDim.x + threadIdx.x;
    if (i >= e) return;
    int r = load_idx(ei, e, 0, i);
    int c = load_idx(ei, e, 1, i);
    if ((unsigned)r >= NN || (unsigned)c >= NN) return;
    int pos = atomicAdd(&g_cursor[c], 1);
    g_src[pos] = r;
    g_val[pos] = ew[i] * g_dinv[r];
}

// ---------------- split kernels ----------------
__global__ void split_x_kernel(const float* __restrict__ src) {
    int i = blockIdx.x * blockDim.x + threadIdx.x;   // quad (2 pairs)
    if (i >= NN * 64) return;
    float4 v = ((const float4*)src)[i];
    unsigned h0, l0, h1, l1;
    split_pair(v.x, v.y, h0, l0);
    split_pair(v.z, v.w, h1, l1);
    ((uint2*)g_ph)[i] = make_uint2(h0, h1);
    ((uint2*)g_pl)[i] = make_uint2(l0, l1);
}

// W[256k][ncol] -> transposed split [n][kpair]. WSET2 = concat(wm,wl) + bcat.
template<int WSET>
__global__ void split_w_kernel(const float* __restrict__ w0, const float* __restrict__ w1,
                               const float* __restrict__ b0, const float* __restrict__ b1) {
    int i = blockIdx.x * blockDim.x + threadIdx.x;
    if (i >= 256 * 128) return;
    int n = i >> 7, j = i & 127;   // n-row, kpair
    float x0, x1;
    if (WSET == 2) {
        x0 = (n < 128) ? w0[(2 * j) * 128 + n]     : w1[(2 * j) * 128 + n - 128];
        x1 = (n < 128) ? w0[(2 * j + 1) * 128 + n] : w1[(2 * j + 1) * 128 + n - 128];
    } else {
        x0 = w0[(2 * j) * 256 + n];
        x1 = w0[(2 * j + 1) * 256 + n];
    }
    unsigned h, l;
    split_pair(x0, x1, h, l);
    if (WSET == 0) { g_wdh[i] = h; g_wdl[i] = l; }
    else if (WSET == 1) { g_weh[i] = h; g_wel[i] = l; }
    else { g_wch[i] = h; g_wcl[i] = l; }
    if (WSET == 2 && i < 256) g_bcat[i] = (i < 128) ? b0[i] : b1[i - 128];
}

// ---------------- SIMT TC GEMM with LDSM fragments, pre-split operands ----------------
// MODE 0: A=P, W=wd, +bias +relu, split -> g_rh/g_rl
// MODE 1: A=R, W=we, f32 -> g_t
// MODE 2: A=P, W=wcat, +g_bcat, split halves -> Cout / Cout+NN*128
template<int MODE>
__global__ __launch_bounds__(256)
void gemm_tc(const float* __restrict__ bias, float* __restrict__ Cout, int M) {
    const unsigned* Ah = (MODE == 1) ? g_rh : g_ph;
    const unsigned* Al = (MODE == 1) ? g_rl : g_pl;
    const unsigned* Wh = (MODE == 0) ? g_wdh : (MODE == 1) ? g_weh : g_wch;
    const unsigned* Wl = (MODE == 0) ? g_wdl : (MODE == 1) ? g_wel : g_wcl;

    // k-major tiles, stride 20 u32 (rows land on distinct bank groups for LDSM)
    __shared__ unsigned As_h[128][20], As_l[128][20];
    __shared__ unsigned Bs_h[128][20], Bs_l[128][20];

    int tid  = threadIdx.x;
    int lane = tid & 31, wid = tid >> 5;
    int warp_m = wid & 3, warp_n = wid >> 2;
    int bm = blockIdx.y * 128;
    int bn = blockIdx.x * 128;
    int gid = lane >> 2, tig = lane & 3;

    uint32_t aH = smem_u32(&As_h[0][0]), aL = smem_u32(&As_l[0][0]);
    uint32_t bH = smem_u32(&Bs_h[0][0]), bL = smem_u32(&Bs_l[0][0]);

    // LDSM quadrant offsets (row, col within tile-group)
    int lr = lane & 7;
    int a_row_off = lr + ((lane >> 3) & 1) * 8;   // + mr
    int a_col_off = (lane >> 4) * 4;              // + kb
    int b_row_off = lr + ((lane >> 4) ? 8 : 0);   // + nb
    int b_col_off = ((lane >> 3) & 1) * 4;        // + kb

    float acc[2][8][4];
    #pragma unroll
    for (int a = 0; a < 2; a++)
        #pragma unroll
        for (int b = 0; b < 8; b++)
            #pragma unroll
            for (int c = 0; c < 4; c++) acc[a][b][c] = 0.f;

    for (int ch = 0; ch < 8; ch++) {     // 8 chunks of 16 kpairs (k32)
        #pragma unroll
        for (int it = 0; it < 2; it++) {
            int idx = tid + it * 256;
            int r = idx >> 2, c4 = (idx & 3) * 4;
            int gr = bm + r;
            uint4 vh = make_uint4(0u,0u,0u,0u), vl = vh;
            if (gr < M) {
                size_t src = (size_t)gr * 128 + ch * 16 + c4;
                vh = *(const uint4*)&Ah[src];
                vl = *(const uint4*)&Al[src];
            }
            *(uint4*)&As_h[r][c4] = vh;
            *(uint4*)&As_l[r][c4] = vl;
        }
        #pragma unroll
        for (int it = 0; it < 2; it++) {
            int idx = tid + it * 256;
            int r = idx >> 2, c4 = (idx & 3) * 4;
            size_t src = (size_t)(bn + r) * 128 + ch * 16 + c4;
            *(uint4*)&Bs_h[r][c4] = *(const uint4*)&Wh[src];
            *(uint4*)&Bs_l[r][c4] = *(const uint4*)&Wl[src];
        }
        __syncthreads();

        #pragma unroll
        for (int kk = 0; kk < 2; kk++) {
            int kb = kk * 8;
            unsigned ah[2][4], al[2][4];
            #pragma unroll
            for (int mt = 0; mt < 2; mt++) {
                int mr = warp_m * 32 + mt * 16;
                uint32_t off = ((mr + a_row_off) * 20 + kb + a_col_off) * 4;
                ldsm_x4(ah[mt], aH + off);
                ldsm_x4(al[mt], aL + off);
            }
            #pragma unroll
            for (int nt2 = 0; nt2 < 4; nt2++) {
                int nb = warp_n * 64 + nt2 * 16;
                uint32_t off = ((nb + b_row_off) * 20 + kb + b_col_off) * 4;
                unsigned bh4[4], bl4[4];
                ldsm_x4(bh4, bH + off);
                ldsm_x4(bl4, bL + off);
                #pragma unroll
                for (int mt = 0; mt < 2; mt++) {
                    mma16(acc[mt][2*nt2],   ah[mt], bl4[0], bl4[1]);
                    mma16(acc[mt][2*nt2],   al[mt], bh4[0], bh4[1]);
                    mma16(acc[mt][2*nt2],   ah[mt], bh4[0], bh4[1]);
                    mma16(acc[mt][2*nt2+1], ah[mt], bl4[2], bl4[3]);
                    mma16(acc[mt][2*nt2+1], al[mt], bh4[2], bh4[3]);
                    mma16(acc[mt][2*nt2+1], ah[mt], bh4[2], bh4[3]);
                }
            }
        }
        __syncthreads();
    }

    #pragma unroll
    for (int mt = 0; mt < 2; mt++) {
        int rr = bm + warp_m * 32 + mt * 16 + gid;
        #pragma unroll
        for (int nt = 0; nt < 8; nt++) {
            int c = bn + warp_n * 64 + nt * 8 + tig * 2;
            float v0 = acc[mt][nt][0], v1 = acc[mt][nt][1];
            float v2 = acc[mt][nt][2], v3 = acc[mt][nt][3];
            if (MODE != 1) {
                const float* bs = (MODE == 2) ? g_bcat : bias;
                float bb0 = bs[c], bb1 = bs[c + 1];
                v0 += bb0; v1 += bb1; v2 += bb0; v3 += bb1;
            }
            if (MODE == 0) {       // relu + split write to R
                v0 = fmaxf(v0, 0.f); v1 = fmaxf(v1, 0.f);
                v2 = fmaxf(v2, 0.f); v3 = fmaxf(v3, 0.f);
                int cp = c >> 1;
                unsigned h, l;
                if (rr < M) {
                    split_pair(v0, v1, h, l);
                    g_rh[(size_t)rr * 128 + cp] = h; g_rl[(size_t)rr * 128 + cp] = l;
                }
                if (rr + 8 < M) {
                    split_pair(v2, v3, h, l);
                    g_rh[(size_t)(rr + 8) * 128 + cp] = h; g_rl[(size_t)(rr + 8) * 128 + cp] = l;
                }
            } else if (MODE == 1) {
                if (rr < M)     *(float2*)&g_t[(size_t)rr * 256 + c]       = make_float2(v0, v1);
                if (rr + 8 < M) *(float2*)&g_t[(size_t)(rr + 8) * 256 + c] = make_float2(v2, v3);
            } else {
                float* base = (c < 128) ? Cout : (Cout + (size_t)NN * 128);
                int cc = (c < 128) ? c : c - 128;
                if (rr < M)     *(float2*)&base[(size_t)rr * 128 + cc]       = make_float2(v0, v1);
                if (rr + 8 < M) *(float2*)&base[(size_t)(rr + 8) * 128 + cc] = make_float2(v2, v3);
            }
        }
    }
}

// ---------------- SpMM ----------------
template<int PHASE>
__global__ __launch_bounds__(256)
void spmm_kernel(const float* __restrict__ bias, int n) {
    const float* feat = (PHASE == 0) ? g_t : g_h1;
    int warp = (blockIdx.x * blockDim.x + threadIdx.x) >> 5;
    int lane = threadIdx.x & 31;
    if (warp >= n) return;
    int beg = g_rowptr[warp];
    int end = g_rowptr[warp + 1];
    const float4* f4 = (const float4*)feat;
    float4 acc0 = make_float4(0.f, 0.f, 0.f, 0.f);
    float4 acc1 = make_float4(0.f, 0.f, 0.f, 0.f);
    int e = beg;
    for (; e + 1 < end; e += 2) {
        int   r0 = g_src[e],     r1 = g_src[e + 1];
        float w0 = g_val[e],     w1 = g_val[e + 1];
        float4 a0 = f4[(size_t)r0 * 64 + lane];
        float4 b0 = f4[(size_t)r0 * 64 + 32 + lane];
        float4 a1 = f4[(size_t)r1 * 64 + lane];
        float4 b1 = f4[(size_t)r1 * 64 + 32 + lane];
        acc0.x = fmaf(w0, a0.x, acc0.x); acc0.y = fmaf(w0, a0.y, acc0.y);
        acc0.z = fmaf(w0, a0.z, acc0.z); acc0.w = fmaf(w0, a0.w, acc0.w);
        acc1.x = fmaf(w0, b0.x, acc1.x); acc1.y = fmaf(w0, b0.y, acc1.y);
        acc1.z = fmaf(w0, b0.z, acc1.z); acc1.w = fmaf(w0, b0.w, acc1.w);
        acc0.x = fmaf(w1, a1.x, acc0.x); acc0.y = fmaf(w1, a1.y, acc0.y);
        acc0.z = fmaf(w1, a1.z, acc0.z); acc0.w = fmaf(w1, a1.w, acc0.w);
        acc1.x = fmaf(w1, b1.x, acc1.x); acc1.y = fmaf(w1, b1.y, acc1.y);
        acc1.z = fmaf(w1, b1.z, acc1.z); acc1.w = fmaf(w1, b1.w, acc1.w);
    }
    if (e < end) {
        int   r = g_src[e];
        float v = g_val[e];
        float4 a = f4[(size_t)r * 64 + lane];
        float4 b = f4[(size_t)r * 64 + 32 + lane];
        acc0.x = fmaf(v, a.x, acc0.x); acc0.y = fmaf(v, a.y, acc0.y);
        acc0.z = fmaf(v, a.z, acc0.z); acc0.w = fmaf(v, a.w, acc0.w);
        acc1.x = fmaf(v, b.x, acc1.x); acc1.y = fmaf(v, b.y, acc1.y);
        acc1.z = fmaf(v, b.z, acc1.z); acc1.w = fmaf(v, b.w, acc1.w);
    }
    float di = g_dinv[warp];
    float d2 = di * di;
    float4 s0 = f4[(size_t)warp * 64 + lane];
    float4 s1 = f4[(size_t)warp * 64 + 32 + lane];
    float4 o0, o1;
    o0.x = di * acc0.x + d2 * s0.x; o0.y = di * acc0.y + d2 * s0.y;
    o0.z = di * acc0.z + d2 * s0.z; o0.w = di * acc0.w + d2 * s0.w;
    o1.x = di * acc1.x + d2 * s1.x; o1.y = di * acc1.y + d2 * s1.y;
    o1.z = di * acc1.z + d2 * s1.z; o1.w = di * acc1.w + d2 * s1.w;
    if (PHASE == 0) {
        const float4* b4 = (const float4*)bias;
        float4 c0 = b4[lane], c1 = b4[32 + lane];
        o0.x += c0.x; o0.y += c0.y; o0.z += c0.z; o0.w += c0.w;
        o1.x += c1.x; o1.y += c1.y; o1.z += c1.z; o1.w += c1.w;
        float4* out4 = (float4*)g_h1;
        out4[(size_t)warp * 64 + lane]      = o0;
        out4[(size_t)warp * 64 + 32 + lane] = o1;
    } else {
        unsigned h, l;
        size_t base = (size_t)warp * 128;
        split_pair(o0.x, o0.y, h, l); g_ph[base + 2 * lane] = h;      g_pl[base + 2 * lane] = l;
        split_pair(o0.z, o0.w, h, l); g_ph[base + 2 * lane + 1] = h;  g_pl[base + 2 * lane + 1] = l;
        split_pair(o1.x, o1.y, h, l); g_ph[base + 64 + 2 * lane] = h;     g_pl[base + 64 + 2 * lane] = l;
        split_pair(o1.z, o1.w, h, l); g_ph[base + 64 + 2 * lane + 1] = h; g_pl[base + 64 + 2 * lane + 1] = l;
    }
}

// ---------------- launch ----------------
extern "C" void kernel_launch(void* const* d_in, const int* in_sizes, int n_in,
                              void* d_out, int out_size) {
    const float* x  = (const float*)d_in[0];
    const void*  ei = d_in[1];
    const float* ew = (const float*)d_in[2];
    const float* wd = (const float*)d_in[3];
    const float* bd = (const float*)d_in[4];
    const float* we = (const float*)d_in[5];
    const float* be = (const float*)d_in[6];
    const float* wm = (const float*)d_in[7];
    const float* bmu = (const float*)d_in[8];
    const float* wl = (const float*)d_in[9];
    const float* bl = (const float*)d_in[10];
    float* out = (float*)d_out;

    const int n = NN;
    const int e = EE;

    dim3 grid(2, (n + 127) / 128);
    int spmm_blocks = (n * 32 + 255) / 256;

    // ordered so the first GEMM sits at launch index 3 (ncu capture slot)
    detect_kernel<<<1, 1024>>>((const int*)ei, 2 * e);                    // 0
    split_x_kernel<<<(NN * 64 + 255) / 256, 256>>>(x);                    // 1
    split_w_kernel<0><<<128, 256>>>(wd, nullptr, nullptr, nullptr);       // 2
    gemm_tc<0><<<grid, 256>>>(bd, nullptr, n);                            // 3: h0 -> R
    split_w_kernel<1><<<128, 256>>>(we, nullptr, nullptr, nullptr);       // 4
    gemm_tc<1><<<grid, 256>>>(nullptr, nullptr, n);                       // 5: t -> g_t
    split_w_kernel<2><<<128, 256>>>(wm, wl, bmu, bl);                     // 6
    init_kernel<<<(n + 255) / 256, 256>>>(n);                             // 7
    edge_pass<<<(e + 255) / 256, 256>>>(ei, ew, e);                       // 8
    dinv_kernel<<<(n + 255) / 256, 256>>>(n);                             // 9
    scan_kernel<<<1, 1024>>>(n);                                          // 10
    scatter_kernel<<<(e + 255) / 256, 256>>>(ei, ew, e);                  // 11
    spmm_kernel<0><<<spmm_blocks, 256>>>(be, n);                          // 12: h1
    spmm_kernel<1><<<spmm_blocks, 256>>>(nullptr, n);                     // 13: z -> P
    gemm_tc<2><<<grid, 256>>>(nullptr, out, n);                           // 14: mu/logstd
}

// round 9
// speedup vs baseline: 1.0903x; 1.0903x over previous
#include <cuda_runtime.h>
#include <cstdint>

#define NN   100000
#define EE   1600000
#define KDIM 256

// ---------------- scratch (device globals) ----------------
__device__ unsigned g_ph[(size_t)NN * 128];  // split A (x, later z)  [row][kpair]
__device__ unsigned g_pl[(size_t)NN * 128];
__device__ unsigned g_rh[(size_t)NN * 128];  // split h0
__device__ unsigned g_rl[(size_t)NN * 128];
__device__ float    g_t [(size_t)NN * KDIM]; // t = h0 @ We
__device__ float    g_h1[(size_t)NN * KDIM]; // h1
// weights pre-split, transposed to [n][kpair]
__device__ unsigned g_wdh[256 * 128], g_wdl[256 * 128];
__device__ unsigned g_weh[256 * 128], g_wel[256 * 128];
__device__ unsigned g_wch[256 * 128], g_wcl[256 * 128];
__device__ float    g_bcat[256];
__device__ float g_deg[NN];
__device__ float g_dinv[NN];
__device__ int   g_cnt[NN];
__device__ int   g_rowptr[NN + 1];
__device__ int   g_cursor[NN];
__device__ int   g_src[EE];
__device__ float g_val[EE];
__device__ int   g_is64;

// ---------------- helpers ----------------
__device__ __forceinline__ void split_pair(float x0, float x1,
                                           unsigned& hi, unsigned& lo) {
    unsigned h;
    asm("cvt.rn.bf16x2.f32 %0, %1, %2;" : "=r"(h) : "f"(x1), "f"(x0));
    float h0 = __uint_as_float(h << 16);
    float h1 = __uint_as_float(h & 0xffff0000u);
    float r0 = x0 - h0, r1 = x1 - h1;
    unsigned l;
    asm("cvt.rn.bf16x2.f32 %0, %1, %2;" : "=r"(l) : "f"(r1), "f"(r0));
    hi = h; lo = l;
}

__device__ __forceinline__ uint32_t smem_u32(const void* p) {
    uint32_t a;
    asm("{ .reg .u64 t; cvta.to.shared.u64 t, %1; cvt.u32.u64 %0, t; }"
        : "=r"(a) : "l"(p));
    return a;
}

__device__ __forceinline__ void ldsm_x4(unsigned r[4], uint32_t addr) {
    asm volatile("ldmatrix.sync.aligned.m8n8.x4.shared.b16 {%0,%1,%2,%3}, [%4];"
        : "=r"(r[0]), "=r"(r[1]), "=r"(r[2]), "=r"(r[3]) : "r"(addr));
}

__device__ __forceinline__ void mma16(float c[4], const unsigned a[4],
                                      unsigned b0, unsigned b1) {
    asm volatile(
        "mma.sync.aligned.m16n8k16.row.col.f32.bf16.bf16.f32 "
        "{%0,%1,%2,%3}, {%4,%5,%6,%7}, {%8,%9}, {%0,%1,%2,%3};"
        : "+f"(c[0]), "+f"(c[1]), "+f"(c[2]), "+f"(c[3])
        : "r"(a[0]), "r"(a[1]), "r"(a[2]), "r"(a[3]), "r"(b0), "r"(b1));
}

__device__ __forceinline__ void cpa16(uint32_t dst, const void* src, int sz) {
    asm volatile("cp.async.cg.shared.global [%0], [%1], 16, %2;"
                 :: "r"(dst), "l"(src), "r"(sz) : "memory");
}
#define CPA_COMMIT() asm volatile("cp.async.commit_group;" ::: "memory")
#define CPA_WAIT0()  asm volatile("cp.async.wait_group 0;" ::: "memory")

// ---------------- edge-index dtype detection ----------------
__global__ void detect_kernel(const int* __restrict__ ei32, int n_int32) {
    __shared__ int any;
    if (threadIdx.x == 0) any = 0;
    __syncthreads();
    for (int i = threadIdx.x; i < 4096; i += blockDim.x) {
        int pos = 2 * i + 1;
        if (pos < n_int32 && ei32[pos] != 0) any = 1;
    }
    __syncthreads();
    if (threadIdx.x == 0) g_is64 = (any == 0) ? 1 : 0;
}

__device__ __forceinline__ int load_idx(const void* ei, int e, int part, int i) {
    if (g_is64) return (int)((const long long*)ei)[(size_t)part * e + i];
    return ((const int*)ei)[(size_t)part * e + i];
}

// ---------------- graph preprocessing ----------------
__global__ void init_kernel(int n) {
    int i = blockIdx.x * blockDim.x + threadIdx.x;
    if (i < n) { g_deg[i] = 1.0f; g_cnt[i] = 0; }
}

__global__ void edge_pass(const void* __restrict__ ei,
                          const float* __restrict__ ew, int e) {
    int i = blockIdx.x * blockDim.x + threadIdx.x;
    if (i >= e) return;
    int c = load_idx(ei, e, 1, i);
    if ((unsigned)c >= NN) return;
    atomicAdd(&g_deg[c], ew[i]);
    atomicAdd(&g_cnt[c], 1);
}

__global__ void dinv_kernel(int n) {
    int i = blockIdx.x * blockDim.x + threadIdx.x;
    if (i < n) g_dinv[i] = rsqrtf(g_deg[i]);
}

__global__ void scan_kernel(int n) {
    __shared__ int part[1024];
    int tid = threadIdx.x;
    int chunk = (n + 1023) >> 10;
    int beg = tid * chunk;
    int end = beg + chunk; if (end > n) end = n;
    int s = 0;
    for (int i = beg; i < end; i++) s += g_cnt[i];
    part[tid] = s;
    __syncthreads();
    for (int off = 1; off < 1024; off <<= 1) {
        int v = (tid >= off) ? part[tid - off] : 0;
        __syncthreads();
        part[tid] += v;
        __syncthreads();
    }
    int run = (tid > 0) ? part[tid - 1] : 0;
    for (int i = beg; i < end; i++) {
        g_rowptr[i] = run; g_cursor[i] = run; run += g_cnt[i];
    }
    if (tid == 1023) g_rowptr[n] = part[1023];
}

__global__ void scatter_kernel(const void* __restrict__ ei,
                               const float* __restrict__ ew, int e) {
    int i = blockIdx.x * blockDim.x + threadIdx.x;
    if (i >= e) return;
    int r = load_idx(ei, e, 0, i);
    int c = load_idx(ei, e, 1, i);
    if ((unsigned)r >= NN || (unsigned)c >= NN) return;
    int pos = atomicAdd(&g_cursor[c], 1);
    g_src[pos] = r;
    g_val[pos] = ew[i] * g_dinv[r];
}

// ---------------- split kernels ----------------
__global__ void split_x_kernel(const float* __restrict__ src) {
    int i = blockIdx.x * blockDim.x + threadIdx.x;   // quad (2 pairs)
    if (i >= NN * 64) return;
    float4 v = ((const float4*)src)[i];
    unsigned h0, l0, h1, l1;
    split_pair(v.x, v.y, h0, l0);
    split_pair(v.z, v.w, h1, l1);
    ((uint2*)g_ph)[i] = make_uint2(h0, h1);
    ((uint2*)g_pl)[i] = make_uint2(l0, l1);
}

template<int WSET>
__global__ void split_w_kernel(const float* __restrict__ w0, const float* __restrict__ w1,
                               const float* __restrict__ b0, const float* __restrict__ b1) {
    int i = blockIdx.x * blockDim.x + threadIdx.x;
    if (i >= 256 * 128) return;
    int n = i >> 7, j = i & 127;   // n-row, kpair
    float x0, x1;
    if (WSET == 2) {
        x0 = (n < 128) ? w0[(2 * j) * 128 + n]     : w1[(2 * j) * 128 + n - 128];
        x1 = (n < 128) ? w0[(2 * j + 1) * 128 + n] : w1[(2 * j + 1) * 128 + n - 128];
    } else {
        x0 = w0[(2 * j) * 256 + n];
        x1 = w0[(2 * j + 1) * 256 + n];
    }
    unsigned h, l;
    split_pair(x0, x1, h, l);
    if (WSET == 0) { g_wdh[i] = h; g_wdl[i] = l; }
    else if (WSET == 1) { g_weh[i] = h; g_wel[i] = l; }
    else { g_wch[i] = h; g_wcl[i] = l; }
    if (WSET == 2 && i < 256) g_bcat[i] = (i < 128) ? b0[i] : b1[i - 128];
}

// ---------------- pipelined TC GEMM (cp.async double-buffer, LDSM, pre-split) -------------
// Smem layout per matrix: [stage 2][plane 2][row 128][16B]; plane = kpair group of 4.
// MODE 0: A=P, W=wd, +bias +relu, split -> g_rh/g_rl
// MODE 1: A=R, W=we, f32 -> g_t
// MODE 2: A=P, W=wcat, +g_bcat, split halves -> Cout / Cout+NN*128
template<int MODE>
__global__ __launch_bounds__(256, 2)
void gemm_tc(const float* __restrict__ bias, float* __restrict__ Cout, int M) {
    const unsigned* Ah = (MODE == 1) ? g_rh : g_ph;
    const unsigned* Al = (MODE == 1) ? g_rl : g_pl;
    const unsigned* Wh = (MODE == 0) ? g_wdh : (MODE == 1) ? g_weh : g_wch;
    const unsigned* Wl = (MODE == 0) ? g_wdl : (MODE == 1) ? g_wel : g_wcl;

    __shared__ unsigned sAh[2 * 2 * 128 * 4];   // 8KB each
    __shared__ unsigned sAl[2 * 2 * 128 * 4];
    __shared__ unsigned sBh[2 * 2 * 128 * 4];
    __shared__ unsigned sBl[2 * 2 * 128 * 4];

    int tid  = threadIdx.x;
    int lane = tid & 31, wid = tid >> 5;
    int warp_m = wid & 3, warp_n = wid >> 2;
    int bm = blockIdx.y * 128;
    int bn = blockIdx.x * 128;
    int gid = lane >> 2, tig = lane & 3;

    uint32_t aH = smem_u32(sAh), aL = smem_u32(sAl);
    uint32_t bH = smem_u32(sBh), bL = smem_u32(sBl);

    // cp.async source/dest mapping: thread -> (row = tid&127, plane = tid>>7)
    int ld_row = tid & 127;
    int ld_plane = tid >> 7;
    int a_valid = (bm + ld_row < M) ? 16 : 0;
    uint32_t st_off = (uint32_t)(ld_plane * 2048 + ld_row * 16);
    size_t a_src_base = (size_t)(bm + ld_row) * 128 + ld_plane * 4;
    size_t b_src_base = (size_t)(bn + ld_row) * 128 + ld_plane * 4;

    // LDSM fragment addresses
    int lr = lane & 7;
    uint32_t a_frag = (uint32_t)((lane >> 4) * 2048
                    + (warp_m * 32 + lr + ((lane >> 3) & 1) * 8) * 16);
    uint32_t b_frag = (uint32_t)(((lane >> 3) & 1) * 2048
                    + (warp_n * 64 + lr + ((lane >> 4) ? 8 : 0)) * 16);

    float acc[2][8][4];
    #pragma unroll
    for (int a = 0; a < 2; a++)
        #pragma unroll
        for (int b = 0; b < 8; b++)
            #pragma unroll
            for (int c = 0; c < 4; c++) acc[a][b][c] = 0.f;

    // prologue: load chunk 0 into stage 0
    cpa16(aH + st_off, &Ah[a_src_base], a_valid);
    cpa16(aL + st_off, &Al[a_src_base], a_valid);
    cpa16(bH + st_off, &Wh[b_src_base], 16);
    cpa16(bL + st_off, &Wl[b_src_base], 16);
    CPA_COMMIT();

    for (int ch = 0; ch < 16; ch++) {          // 16 chunks of k16 (8 kpairs)
        CPA_WAIT0();
        __syncthreads();
        if (ch + 1 < 16) {
            uint32_t dst = st_off + ((ch + 1) & 1) * 4096;
            size_t srcA = a_src_base + (ch + 1) * 8;
            size_t srcB = b_src_base + (ch + 1) * 8;
            cpa16(aH + dst, &Ah[srcA], a_valid);
            cpa16(aL + dst, &Al[srcA], a_valid);
            cpa16(bH + dst, &Wh[srcB], 16);
            cpa16(bL + dst, &Wl[srcB], 16);
            CPA_COMMIT();
        }
        uint32_t so = (ch & 1) * 4096;

        unsigned ah[2][4], al[2][4];
        #pragma unroll
        for (int mt = 0; mt < 2; mt++) {
            ldsm_x4(ah[mt], aH + so + a_frag + mt * 256);   // +16 rows
            ldsm_x4(al[mt], aL + so + a_frag + mt * 256);
        }
        #pragma unroll
        for (int nt2 = 0; nt2 < 4; nt2++) {
            unsigned bh4[4], bl4[4];
            ldsm_x4(bh4, bH + so + b_frag + nt2 * 256);
            ldsm_x4(bl4, bL + so + b_frag + nt2 * 256);
            #pragma unroll
            for (int mt = 0; mt < 2; mt++) {
                float* c0 = acc[mt][2 * nt2];
                float* c1 = acc[mt][2 * nt2 + 1];
                mma16(c0, ah[mt], bl4[0], bl4[1]);
                mma16(c1, ah[mt], bl4[2], bl4[3]);
                mma16(c0, al[mt], bh4[0], bh4[1]);
                mma16(c1, al[mt], bh4[2], bh4[3]);
                mma16(c0, ah[mt], bh4[0], bh4[1]);
                mma16(c1, ah[mt], bh4[2], bh4[3]);
            }
        }
        __syncthreads();
    }

    #pragma unroll
    for (int mt = 0; mt < 2; mt++) {
        int rr = bm + warp_m * 32 + mt * 16 + gid;
        #pragma unroll
        for (int nt = 0; nt < 8; nt++) {
            int c = bn + warp_n * 64 + nt * 8 + tig * 2;
            float v0 = acc[mt][nt][0], v1 = acc[mt][nt][1];
            float v2 = acc[mt][nt][2], v3 = acc[mt][nt][3];
            if (MODE != 1) {
                const float* bs = (MODE == 2) ? g_bcat : bias;
                float bb0 = bs[c], bb1 = bs[c + 1];
                v0 += bb0; v1 += bb1; v2 += bb0; v3 += bb1;
            }
            if (MODE == 0) {
                v0 = fmaxf(v0, 0.f); v1 = fmaxf(v1, 0.f);
                v2 = fmaxf(v2, 0.f); v3 = fmaxf(v3, 0.f);
                int cp = c >> 1;
                unsigned h, l;
                if (rr < M) {
                    split_pair(v0, v1, h, l);
                    g_rh[(size_t)rr * 128 + cp] = h; g_rl[(size_t)rr * 128 + cp] = l;
                }
                if (rr + 8 < M) {
                    split_pair(v2, v3, h, l);
                    g_rh[(size_t)(rr + 8) * 128 + cp] = h; g_rl[(size_t)(rr + 8) * 128 + cp] = l;
                }
            } else if (MODE == 1) {
                if (rr < M)     *(float2*)&g_t[(size_t)rr * 256 + c]       = make_float2(v0, v1);
                if (rr + 8 < M) *(float2*)&g_t[(size_t)(rr + 8) * 256 + c] = make_float2(v2, v3);
            } else {
                float* base = (c < 128) ? Cout : (Cout + (size_t)NN * 128);
                int cc = (c < 128) ? c : c - 128;
                if (rr < M)     *(float2*)&base[(size_t)rr * 128 + cc]       = make_float2(v0, v1);
                if (rr + 8 < M) *(float2*)&base[(size_t)(rr + 8) * 128 + cc] = make_float2(v2, v3);
            }
        }
    }
}

// ---------------- SpMM ----------------
template<int PHASE>
__global__ __launch_bounds__(256)
void spmm_kernel(const float* __restrict__ bias, int n) {
    const float* feat = (PHASE == 0) ? g_t : g_h1;
    int warp = (blockIdx.x * blockDim.x + threadIdx.x) >> 5;
    int lane = threadIdx.x & 31;
    if (warp >= n) return;
    int beg = g_rowptr[warp];
    int end = g_rowptr[warp + 1];
    const float4* f4 = (const float4*)feat;
    float4 acc0 = make_float4(0.f, 0.f, 0.f, 0.f);
    float4 acc1 = make_float4(0.f, 0.f, 0.f, 0.f);
    int e = beg;
    for (; e + 1 < end; e += 2) {
        int   r0 = g_src[e],     r1 = g_src[e + 1];
        float w0 = g_val[e],     w1 = g_val[e + 1];
        float4 a0 = f4[(size_t)r0 * 64 + lane];
        float4 b0 = f4[(size_t)r0 * 64 + 32 + lane];
        float4 a1 = f4[(size_t)r1 * 64 + lane];
        float4 b1 = f4[(size_t)r1 * 64 + 32 + lane];
        acc0.x = fmaf(w0, a0.x, acc0.x); acc0.y = fmaf(w0, a0.y, acc0.y);
        acc0.z = fmaf(w0, a0.z, acc0.z); acc0.w = fmaf(w0, a0.w, acc0.w);
        acc1.x = fmaf(w0, b0.x, acc1.x); acc1.y = fmaf(w0, b0.y, acc1.y);
        acc1.z = fmaf(w0, b0.z, acc1.z); acc1.w = fmaf(w0, b0.w, acc1.w);
        acc0.x = fmaf(w1, a1.x, acc0.x); acc0.y = fmaf(w1, a1.y, acc0.y);
        acc0.z = fmaf(w1, a1.z, acc0.z); acc0.w = fmaf(w1, a1.w, acc0.w);
        acc1.x = fmaf(w1, b1.x, acc1.x); acc1.y = fmaf(w1, b1.y, acc1.y);
        acc1.z = fmaf(w1, b1.z, acc1.z); acc1.w = fmaf(w1, b1.w, acc1.w);
    }
    if (e < end) {
        int   r = g_src[e];
        float v = g_val[e];
        float4 a = f4[(size_t)r * 64 + lane];
        float4 b = f4[(size_t)r * 64 + 32 + lane];
        acc0.x = fmaf(v, a.x, acc0.x); acc0.y = fmaf(v, a.y, acc0.y);
        acc0.z = fmaf(v, a.z, acc0.z); acc0.w = fmaf(v, a.w, acc0.w);
        acc1.x = fmaf(v, b.x, acc1.x); acc1.y = fmaf(v, b.y, acc1.y);
        acc1.z = fmaf(v, b.z, acc1.z); acc1.w = fmaf(v, b.w, acc1.w);
    }
    float di = g_dinv[warp];
    float d2 = di * di;
    float4 s0 = f4[(size_t)warp * 64 + lane];
    float4 s1 = f4[(size_t)warp * 64 + 32 + lane];
    float4 o0, o1;
    o0.x = di * acc0.x + d2 * s0.x; o0.y = di * acc0.y + d2 * s0.y;
    o0.z = di * acc0.z + d2 * s0.z; o0.w = di * acc0.w + d2 * s0.w;
    o1.x = di * acc1.x + d2 * s1.x; o1.y = di * acc1.y + d2 * s1.y;
    o1.z = di * acc1.z + d2 * s1.z; o1.w = di * acc1.w + d2 * s1.w;
    if (PHASE == 0) {
        const float4* b4 = (const float4*)bias;
        float4 c0 = b4[lane], c1 = b4[32 + lane];
        o0.x += c0.x; o0.y += c0.y; o0.z += c0.z; o0.w += c0.w;
        o1.x += c1.x; o1.y += c1.y; o1.z += c1.z; o1.w += c1.w;
        float4* out4 = (float4*)g_h1;
        out4[(size_t)warp * 64 + lane]      = o0;
        out4[(size_t)warp * 64 + 32 + lane] = o1;
    } else {
        unsigned h, l;
        size_t base = (size_t)warp * 128;
        split_pair(o0.x, o0.y, h, l); g_ph[base + 2 * lane] = h;      g_pl[base + 2 * lane] = l;
        split_pair(o0.z, o0.w, h, l); g_ph[base + 2 * lane + 1] = h;  g_pl[base + 2 * lane + 1] = l;
        split_pair(o1.x, o1.y, h, l); g_ph[base + 64 + 2 * lane] = h;     g_pl[base + 64 + 2 * lane] = l;
        split_pair(o1.z, o1.w, h, l); g_ph[base + 64 + 2 * lane + 1] = h; g_pl[base + 64 + 2 * lane + 1] = l;
    }
}

// ---------------- launch ----------------
extern "C" void kernel_launch(void* const* d_in, const int* in_sizes, int n_in,
                              void* d_out, int out_size) {
    const float* x  = (const float*)d_in[0];
    const void*  ei = d_in[1];
    const float* ew = (const float*)d_in[2];
    const float* wd = (const float*)d_in[3];
    const float* bd = (const float*)d_in[4];
    const float* we = (const float*)d_in[5];
    const float* be = (const float*)d_in[6];
    const float* wm = (const float*)d_in[7];
    const float* bmu = (const float*)d_in[8];
    const float* wl = (const float*)d_in[9];
    const float* bl = (const float*)d_in[10];
    float* out = (float*)d_out;

    const int n = NN;
    const int e = EE;

    dim3 grid(2, (n + 127) / 128);
    int spmm_blocks = (n * 32 + 255) / 256;

    // ordered so the first GEMM sits at launch index 3 (ncu capture slot)
    detect_kernel<<<1, 1024>>>((const int*)ei, 2 * e);                    // 0
    split_x_kernel<<<(NN * 64 + 255) / 256, 256>>>(x);                    // 1
    split_w_kernel<0><<<128, 256>>>(wd, nullptr, nullptr, nullptr);       // 2
    gemm_tc<0><<<grid, 256>>>(bd, nullptr, n);                            // 3: h0 -> R
    split_w_kernel<1><<<128, 256>>>(we, nullptr, nullptr, nullptr);       // 4
    gemm_tc<1><<<grid, 256>>>(nullptr, nullptr, n);                       // 5: t -> g_t
    split_w_kernel<2><<<128, 256>>>(wm, wl, bmu, bl);                     // 6
    init_kernel<<<(n + 255) / 256, 256>>>(n);                             // 7
    edge_pass<<<(e + 255) / 256, 256>>>(ei, ew, e);                       // 8
    dinv_kernel<<<(n + 255) / 256, 256>>>(n);                             // 9
    scan_kernel<<<1, 1024>>>(n);                                          // 10
    scatter_kernel<<<(e + 255) / 256, 256>>>(ei, ew, e);                  // 11
    spmm_kernel<0><<<spmm_blocks, 256>>>(be, n);                          // 12: h1
    spmm_kernel<1><<<spmm_blocks, 256>>>(nullptr, n);                     // 13: z -> P
    gemm_tc<2><<<grid, 256>>>(nullptr, out, n);                           // 14: mu/logstd
}

// round 11
// speedup vs baseline: 1.0905x; 1.0003x over previous
#include <cuda_runtime.h>
#include <cstdint>

#define NN   100000
#define EE   1600000
#define KDIM 256

// ---------------- scratch (device globals) ----------------
__device__ unsigned g_ph[(size_t)NN * 128];  // split A (x, later z)  [row][kpair]
__device__ unsigned g_pl[(size_t)NN * 128];
__device__ unsigned g_rh[(size_t)NN * 128];  // split h0
__device__ unsigned g_rl[(size_t)NN * 128];
__device__ float    g_t [(size_t)NN * KDIM]; // t = h0 @ We
__device__ float    g_h1[(size_t)NN * KDIM]; // h1
// weights pre-split, transposed to [n][kpair]
__device__ unsigned g_wdh[256 * 128], g_wdl[256 * 128];
__device__ unsigned g_weh[256 * 128], g_wel[256 * 128];
__device__ unsigned g_wch[256 * 128], g_wcl[256 * 128];
__device__ float    g_bcat[256];
__device__ float g_deg[NN];
__device__ float g_dinv[NN];
__device__ int   g_cnt[NN];
__device__ int   g_rowptr[NN + 1];
__device__ int   g_cursor[NN];
__device__ int   g_src[EE];
__device__ float g_val[EE];
__device__ int   g_is64;

// ---------------- helpers ----------------
__device__ __forceinline__ void split_pair(float x0, float x1,
                                           unsigned& hi, unsigned& lo) {
    unsigned h;
    asm("cvt.rn.bf16x2.f32 %0, %1, %2;" : "=r"(h) : "f"(x1), "f"(x0));
    float h0 = __uint_as_float(h << 16);
    float h1 = __uint_as_float(h & 0xffff0000u);
    float r0 = x0 - h0, r1 = x1 - h1;
    unsigned l;
    asm("cvt.rn.bf16x2.f32 %0, %1, %2;" : "=r"(l) : "f"(r1), "f"(r0));
    hi = h; lo = l;
}

__device__ __forceinline__ uint32_t smem_u32(const void* p) {
    uint32_t a;
    asm("{ .reg .u64 t; cvta.to.shared.u64 t, %1; cvt.u32.u64 %0, t; }"
        : "=r"(a) : "l"(p));
    return a;
}

__device__ __forceinline__ void ldsm_x4(unsigned r[4], uint32_t addr) {
    asm volatile("ldmatrix.sync.aligned.m8n8.x4.shared.b16 {%0,%1,%2,%3}, [%4];"
        : "=r"(r[0]), "=r"(r[1]), "=r"(r[2]), "=r"(r[3]) : "r"(addr));
}

__device__ __forceinline__ void mma16(float c[4], const unsigned a[4],
                                      unsigned b0, unsigned b1) {
    asm volatile(
        "mma.sync.aligned.m16n8k16.row.col.f32.bf16.bf16.f32 "
        "{%0,%1,%2,%3}, {%4,%5,%6,%7}, {%8,%9}, {%0,%1,%2,%3};"
        : "+f"(c[0]), "+f"(c[1]), "+f"(c[2]), "+f"(c[3])
        : "r"(a[0]), "r"(a[1]), "r"(a[2]), "r"(a[3]), "r"(b0), "r"(b1));
}

__device__ __forceinline__ void cpa16(uint32_t dst, const void* src, int sz) {
    asm volatile("cp.async.cg.shared.global [%0], [%1], 16, %2;"
                 :: "r"(dst), "l"(src), "r"(sz) : "memory");
}
#define CPA_COMMIT() asm volatile("cp.async.commit_group;" ::: "memory")
#define CPA_WAIT1()  asm volatile("cp.async.wait_group 1;" ::: "memory")

// ---------------- edge-index dtype detection ----------------
__global__ void detect_kernel(const int* __restrict__ ei32, int n_int32) {
    __shared__ int any;
    if (threadIdx.x == 0) any = 0;
    __syncthreads();
    for (int i = threadIdx.x; i < 4096; i += blockDim.x) {
        int pos = 2 * i + 1;
        if (pos < n_int32 && ei32[pos] != 0) any = 1;
    }
    __syncthreads();
    if (threadIdx.x == 0) g_is64 = (any == 0) ? 1 : 0;
}

__device__ __forceinline__ int load_idx(const void* ei, int e, int part, int i) {
    if (g_is64) return (int)((const long long*)ei)[(size_t)part * e + i];
    return ((const int*)ei)[(size_t)part * e + i];
}

// ---------------- graph preprocessing ----------------
__global__ void init_kernel(int n) {
    int i = blockIdx.x * blockDim.x + threadIdx.x;
    if (i < n) { g_deg[i] = 1.0f; g_cnt[i] = 0; }
}

__global__ void edge_pass(const void* __restrict__ ei,
                          const float* __restrict__ ew, int e) {
    int i = blockIdx.x * blockDim.x + threadIdx.x;
    if (i >= e) return;
    int c = load_idx(ei, e, 1, i);
    if ((unsigned)c >= NN) return;
    atomicAdd(&g_deg[c], ew[i]);
    atomicAdd(&g_cnt[c], 1);
}

__global__ void dinv_kernel(int n) {
    int i = blockIdx.x * blockDim.x + threadIdx.x;
    if (i < n) g_dinv[i] = rsqrtf(g_deg[i]);
}

__global__ void scan_kernel(int n) {
    __shared__ int part[1024];
    int tid = threadIdx.x;
    int chunk = (n + 1023) >> 10;
    int beg = tid * chunk;
    int end = beg + chunk; if (end > n) end = n;
    int s = 0;
    for (int i = beg; i < end; i++) s += g_cnt[i];
    part[tid] = s;
    __syncthreads();
    for (int off = 1; off < 1024; off <<= 1) {
        int v = (tid >= off) ? part[tid - off] : 0;
        __syncthreads();
        part[tid] += v;
        __syncthreads();
    }
    int run = (tid > 0) ? part[tid - 1] : 0;
    for (int i = beg; i < end; i++) {
        g_rowptr[i] = run; g_cursor[i] = run; run += g_cnt[i];
    }
    if (tid == 1023) g_rowptr[n] = part[1023];
}

__global__ void scatter_kernel(const void* __restrict__ ei,
                               const float* __restrict__ ew, int e) {
    int i = blockIdx.x * blockDim.x + threadIdx.x;
    if (i >= e) return;
    int r = load_idx(ei, e, 0, i);
    int c = load_idx(ei, e, 1, i);
    if ((unsigned)r >= NN || (unsigned)c >= NN) return;
    int pos = atomicAdd(&g_cursor[c], 1);
    g_src[pos] = r;
    g_val[pos] = ew[i] * g_dinv[r];
}

// ---------------- split kernels ----------------
__global__ void split_x_kernel(const float* __restrict__ src) {
    int i = blockIdx.x * blockDim.x + threadIdx.x;   // quad (2 pairs)
    if (i >= NN * 64) return;
    float4 v = ((const float4*)src)[i];
    unsigned h0, l0, h1, l1;
    split_pair(v.x, v.y, h0, l0);
    split_pair(v.z, v.w, h1, l1);
    ((uint2*)g_ph)[i] = make_uint2(h0, h1);
    ((uint2*)g_pl)[i] = make_uint2(l0, l1);
}

template<int WSET>
__global__ void split_w_kernel(const float* __restrict__ w0, const float* __restrict__ w1,
                               const float* __restrict__ b0, const float* __restrict__ b1) {
    int i = blockIdx.x * blockDim.x + threadIdx.x;
    if (i >= 256 * 128) return;
    int n = i >> 7, j = i & 127;   // n-row, kpair
    float x0, x1;
    if (WSET == 2) {
        x0 = (n < 128) ? w0[(2 * j) * 128 + n]     : w1[(2 * j) * 128 + n - 128];
        x1 = (n < 128) ? w0[(2 * j + 1) * 128 + n] : w1[(2 * j + 1) * 128 + n - 128];
    } else {
        x0 = w0[(2 * j) * 256 + n];
        x1 = w0[(2 * j + 1) * 256 + n];
    }
    unsigned h, l;
    split_pair(x0, x1, h, l);
    if (WSET == 0) { g_wdh[i] = h; g_wdl[i] = l; }
    else if (WSET == 1) { g_weh[i] = h; g_wel[i] = l; }
    else { g_wch[i] = h; g_wcl[i] = l; }
    if (WSET == 2 && i < 256) g_bcat[i] = (i < 128) ? b0[i] : b1[i - 128];
}

// ---------------- 3-stage pipelined TC GEMM (cp.async, LDSM, pre-split) -------------
// Smem per matrix: [stage 3][plane 2][row 128][16B] = 12KB; 4 matrices = 48KB.
// Stage schedule: consume stage ch%3, prefetch chunk ch+2 into stage (ch+2)%3.
// MODE 0: A=P, W=wd, +bias +relu, split -> g_rh/g_rl
// MODE 1: A=R, W=we, f32 -> g_t
// MODE 2: A=P, W=wcat, +g_bcat, split halves -> Cout / Cout+NN*128
template<int MODE>
__global__ __launch_bounds__(256, 2)
void gemm_tc(const float* __restrict__ bias, float* __restrict__ Cout, int M) {
    const unsigned* Ah = (MODE == 1) ? g_rh : g_ph;
    const unsigned* Al = (MODE == 1) ? g_rl : g_pl;
    const unsigned* Wh = (MODE == 0) ? g_wdh : (MODE == 1) ? g_weh : g_wch;
    const unsigned* Wl = (MODE == 0) ? g_wdl : (MODE == 1) ? g_wel : g_wcl;

    __shared__ unsigned sAh[3 * 2 * 128 * 4];   // 12KB each
    __shared__ unsigned sAl[3 * 2 * 128 * 4];
    __shared__ unsigned sBh[3 * 2 * 128 * 4];
    __shared__ unsigned sBl[3 * 2 * 128 * 4];

    int tid  = threadIdx.x;
    int lane = tid & 31, wid = tid >> 5;
    int warp_m = wid & 3, warp_n = wid >> 2;
    int bm = blockIdx.y * 128;
    int bn = blockIdx.x * 128;
    int gid = lane >> 2, tig = lane & 3;

    uint32_t aH = smem_u32(sAh), aL = smem_u32(sAl);
    uint32_t bH = smem_u32(sBh), bL = smem_u32(sBl);

    // cp.async mapping: thread -> (row = tid&127, plane = tid>>7)
    int ld_row = tid & 127;
    int ld_plane = tid >> 7;
    int a_valid = (bm + ld_row < M) ? 16 : 0;
    uint32_t st_off = (uint32_t)(ld_plane * 2048 + ld_row * 16);
    size_t a_src_base = (size_t)(bm + ld_row) * 128 + ld_plane * 4;
    size_t b_src_base = (size_t)(bn + ld_row) * 128 + ld_plane * 4;

    // LDSM fragment addresses
    int lr = lane & 7;
    uint32_t a_frag = (uint32_t)((lane >> 4) * 2048
                    + (warp_m * 32 + lr + ((lane >> 3) & 1) * 8) * 16);
    uint32_t b_frag = (uint32_t)(((lane >> 3) & 1) * 2048
                    + (warp_n * 64 + lr + ((lane >> 4) ? 8 : 0)) * 16);

    float acc[2][8][4];
    #pragma unroll
    for (int a = 0; a < 2; a++)
        #pragma unroll
        for (int b = 0; b < 8; b++)
            #pragma unroll
            for (int c = 0; c < 4; c++) acc[a][b][c] = 0.f;

    // prologue: chunks 0,1 into stages 0,1
    #pragma unroll
    for (int s = 0; s < 2; s++) {
        uint32_t dst = st_off + s * 4096;
        size_t srcA = a_src_base + s * 8;
        size_t srcB = b_src_base + s * 8;
        cpa16(aH + dst, &Ah[srcA], a_valid);
        cpa16(aL + dst, &Al[srcA], a_valid);
        cpa16(bH + dst, &Wh[srcB], 16);
        cpa16(bL + dst, &Wl[srcB], 16);
        CPA_COMMIT();
    }

    int st_cur = 0;   // = ch % 3
    int st_wr  = 2;   // = (ch + 2) % 3
    for (int ch = 0; ch < 16; ch++) {          // 16 chunks of k16 (8 kpairs)
        CPA_WAIT1();
        __syncthreads();
        if (ch + 2 < 16) {
            uint32_t dst = st_off + (uint32_t)st_wr * 4096;
            size_t srcA = a_src_base + (ch + 2) * 8;
            size_t srcB = b_src_base + (ch + 2) * 8;
            cpa16(aH + dst, &Ah[srcA], a_valid);
            cpa16(aL + dst, &Al[srcA], a_valid);
            cpa16(bH + dst, &Wh[srcB], 16);
            cpa16(bL + dst, &Wl[srcB], 16);
        }
        CPA_COMMIT();                           // always commit (group accounting)

        uint32_t so = (uint32_t)st_cur * 4096;

        unsigned ah[2][4], al[2][4];
        #pragma unroll
        for (int mt = 0; mt < 2; mt++) {
            ldsm_x4(ah[mt], aH + so + a_frag + mt * 256);   // +16 rows
            ldsm_x4(al[mt], aL + so + a_frag + mt * 256);
        }
        #pragma unroll
        for (int nt2 = 0; nt2 < 4; nt2++) {
            unsigned bh4[4], bl4[4];
            ldsm_x4(bh4, bH + so + b_frag + nt2 * 256);
            ldsm_x4(bl4, bL + so + b_frag + nt2 * 256);
            #pragma unroll
            for (int mt = 0; mt < 2; mt++) {
                float* c0 = acc[mt][2 * nt2];
                float* c1 = acc[mt][2 * nt2 + 1];
                mma16(c0, ah[mt], bl4[0], bl4[1]);
                mma16(c1, ah[mt], bl4[2], bl4[3]);
                mma16(c0, al[mt], bh4[0], bh4[1]);
                mma16(c1, al[mt], bh4[2], bh4[3]);
                mma16(c0, ah[mt], bh4[0], bh4[1]);
                mma16(c1, ah[mt], bh4[2], bh4[3]);
            }
        }
        // advance stage counters (wrap mod 3)
        st_cur++; if (st_cur == 3) st_cur = 0;
        st_wr++;  if (st_wr == 3)  st_wr = 0;
    }
    __syncthreads();

    #pragma unroll
    for (int mt = 0; mt < 2; mt++) {
        int rr = bm + warp_m * 32 + mt * 16 + gid;
        #pragma unroll
        for (int nt = 0; nt < 8; nt++) {
            int c = bn + warp_n * 64 + nt * 8 + tig * 2;
            float v0 = acc[mt][nt][0], v1 = acc[mt][nt][1];
            float v2 = acc[mt][nt][2], v3 = acc[mt][nt][3];
            if (MODE != 1) {
                const float* bs = (MODE == 2) ? g_bcat : bias;
                float bb0 = bs[c], bb1 = bs[c + 1];
                v0 += bb0; v1 += bb1; v2 += bb0; v3 += bb1;
            }
            if (MODE == 0) {
                v0 = fmaxf(v0, 0.f); v1 = fmaxf(v1, 0.f);
                v2 = fmaxf(v2, 0.f); v3 = fmaxf(v3, 0.f);
                int cp = c >> 1;
                unsigned h, l;
                if (rr < M) {
                    split_pair(v0, v1, h, l);
                    g_rh[(size_t)rr * 128 + cp] = h; g_rl[(size_t)rr * 128 + cp] = l;
                }
                if (rr + 8 < M) {
                    split_pair(v2, v3, h, l);
                    g_rh[(size_t)(rr + 8) * 128 + cp] = h; g_rl[(size_t)(rr + 8) * 128 + cp] = l;
                }
            } else if (MODE == 1) {
                if (rr < M)     *(float2*)&g_t[(size_t)rr * 256 + c]       = make_float2(v0, v1);
                if (rr + 8 < M) *(float2*)&g_t[(size_t)(rr + 8) * 256 + c] = make_float2(v2, v3);
            } else {
                float* base = (c < 128) ? Cout : (Cout + (size_t)NN * 128);
                int cc = (c < 128) ? c : c - 128;
                if (rr < M)     *(float2*)&base[(size_t)rr * 128 + cc]       = make_float2(v0, v1);
                if (rr + 8 < M) *(float2*)&base[(size_t)(rr + 8) * 128 + cc] = make_float2(v2, v3);
            }
        }
    }
}

// ---------------- SpMM ----------------
template<int PHASE>
__global__ __launch_bounds__(256)
void spmm_kernel(const float* __restrict__ bias, int n) {
    const float* feat = (PHASE == 0) ? g_t : g_h1;
    int warp = (blockIdx.x * blockDim.x + threadIdx.x) >> 5;
    int lane = threadIdx.x & 31;
    if (warp >= n) return;
    int beg = g_rowptr[warp];
    int end = g_rowptr[warp + 1];
    const float4* f4 = (const float4*)feat;
    float4 acc0 = make_float4(0.f, 0.f, 0.f, 0.f);
    float4 acc1 = make_float4(0.f, 0.f, 0.f, 0.f);
    int e = beg;
    for (; e + 1 < end; e += 2) {
        int   r0 = g_src[e],     r1 = g_src[e + 1];
        float w0 = g_val[e],     w1 = g_val[e + 1];
        float4 a0 = f4[(size_t)r0 * 64 + lane];
        float4 b0 = f4[(size_t)r0 * 64 + 32 + lane];
        float4 a1 = f4[(size_t)r1 * 64 + lane];
        float4 b1 = f4[(size_t)r1 * 64 + 32 + lane];
        acc0.x = fmaf(w0, a0.x, acc0.x); acc0.y = fmaf(w0, a0.y, acc0.y);
        acc0.z = fmaf(w0, a0.z, acc0.z); acc0.w = fmaf(w0, a0.w, acc0.w);
        acc1.x = fmaf(w0, b0.x, acc1.x); acc1.y = fmaf(w0, b0.y, acc1.y);
        acc1.z = fmaf(w0, b0.z, acc1.z); acc1.w = fmaf(w0, b0.w, acc1.w);
        acc0.x = fmaf(w1, a1.x, acc0.x); acc0.y = fmaf(w1, a1.y, acc0.y);
        acc0.z = fmaf(w1, a1.z, acc0.z); acc0.w = fmaf(w1, a1.w, acc0.w);
        acc1.x = fmaf(w1, b1.x, acc1.x); acc1.y = fmaf(w1, b1.y, acc1.y);
        acc1.z = fmaf(w1, b1.z, acc1.z); acc1.w = fmaf(w1, b1.w, acc1.w);
    }
    if (e < end) {
        int   r = g_src[e];
        float v = g_val[e];
        float4 a = f4[(size_t)r * 64 + lane];
        float4 b = f4[(size_t)r * 64 + 32 + lane];
        acc0.x = fmaf(v, a.x, acc0.x); acc0.y = fmaf(v, a.y, acc0.y);
        acc0.z = fmaf(v, a.z, acc0.z); acc0.w = fmaf(v, a.w, acc0.w);
        acc1.x = fmaf(v, b.x, acc1.x); acc1.y = fmaf(v, b.y, acc1.y);
        acc1.z = fmaf(v, b.z, acc1.z); acc1.w = fmaf(v, b.w, acc1.w);
    }
    float di = g_dinv[warp];
    float d2 = di * di;
    float4 s0 = f4[(size_t)warp * 64 + lane];
    float4 s1 = f4[(size_t)warp * 64 + 32 + lane];
    float4 o0, o1;
    o0.x = di * acc0.x + d2 * s0.x; o0.y = di * acc0.y + d2 * s0.y;
    o0.z = di * acc0.z + d2 * s0.z; o0.w = di * acc0.w + d2 * s0.w;
    o1.x = di * acc1.x + d2 * s1.x; o1.y = di * acc1.y + d2 * s1.y;
    o1.z = di * acc1.z + d2 * s1.z; o1.w = di * acc1.w + d2 * s1.w;
    if (PHASE == 0) {
        const float4* b4 = (const float4*)bias;
        float4 c0 = b4[lane], c1 = b4[32 + lane];
        o0.x += c0.x; o0.y += c0.y; o0.z += c0.z; o0.w += c0.w;
        o1.x += c1.x; o1.y += c1.y; o1.z += c1.z; o1.w += c1.w;
        float4* out4 = (float4*)g_h1;
        out4[(size_t)warp * 64 + lane]      = o0;
        out4[(size_t)warp * 64 + 32 + lane] = o1;
    } else {
        unsigned h, l;
        size_t base = (size_t)warp * 128;
        split_pair(o0.x, o0.y, h, l); g_ph[base + 2 * lane] = h;      g_pl[base + 2 * lane] = l;
        split_pair(o0.z, o0.w, h, l); g_ph[base + 2 * lane + 1] = h;  g_pl[base + 2 * lane + 1] = l;
        split_pair(o1.x, o1.y, h, l); g_ph[base + 64 + 2 * lane] = h;     g_pl[base + 64 + 2 * lane] = l;
        split_pair(o1.z, o1.w, h, l); g_ph[base + 64 + 2 * lane + 1] = h; g_pl[base + 64 + 2 * lane + 1] = l;
    }
}

// ---------------- launch ----------------
extern "C" void kernel_launch(void* const* d_in, const int* in_sizes, int n_in,
                              void* d_out, int out_size) {
    const float* x  = (const float*)d_in[0];
    const void*  ei = d_in[1];
    const float* ew = (const float*)d_in[2];
    const float* wd = (const float*)d_in[3];
    const float* bd = (const float*)d_in[4];
    const float* we = (const float*)d_in[5];
    const float* be = (const float*)d_in[6];
    const float* wm = (const float*)d_in[7];
    const float* bmu = (const float*)d_in[8];
    const float* wl = (const float*)d_in[9];
    const float* bl = (const float*)d_in[10];
    float* out = (float*)d_out;

    const int n = NN;
    const int e = EE;

    dim3 grid(2, (n + 127) / 128);
    int spmm_blocks = (n * 32 + 255) / 256;

    // ordered so the first GEMM sits at launch index 3 (ncu capture slot)
    detect_kernel<<<1, 1024>>>((const int*)ei, 2 * e);                    // 0
    split_x_kernel<<<(NN * 64 + 255) / 256, 256>>>(x);                    // 1
    split_w_kernel<0><<<128, 256>>>(wd, nullptr, nullptr, nullptr);       // 2
    gemm_tc<0><<<grid, 256>>>(bd, nullptr, n);                            // 3: h0 -> R
    split_w_kernel<1><<<128, 256>>>(we, nullptr, nullptr, nullptr);       // 4
    gemm_tc<1><<<grid, 256>>>(nullptr, nullptr, n);                       // 5: t -> g_t
    split_w_kernel<2><<<128, 256>>>(wm, wl, bmu, bl);                     // 6
    init_kernel<<<(n + 255) / 256, 256>>>(n);                             // 7
    edge_pass<<<(e + 255) / 256, 256>>>(ei, ew, e);                       // 8
    dinv_kernel<<<(n + 255) / 256, 256>>>(n);                             // 9
    scan_kernel<<<1, 1024>>>(n);                                          // 10
    scatter_kernel<<<(e + 255) / 256, 256>>>(ei, ew, e);                  // 11
    spmm_kernel<0><<<spmm_blocks, 256>>>(be, n);                          // 12: h1
    spmm_kernel<1><<<spmm_blocks, 256>>>(nullptr, n);                     // 13: z -> P
    gemm_tc<2><<<grid, 256>>>(nullptr, out, n);                           // 14: mu/logstd
}

// round 12
// speedup vs baseline: 1.0911x; 1.0005x over previous
#include <cuda_runtime.h>
#include <cstdint>

#define NN   100000
#define EE   1600000
#define KDIM 256

// ---------------- scratch (device globals) ----------------
__device__ unsigned g_ph[(size_t)NN * 128];  // split A (x, later z)  [row][kpair]
__device__ unsigned g_pl[(size_t)NN * 128];
__device__ unsigned g_rh[(size_t)NN * 128];  // split h0
__device__ unsigned g_rl[(size_t)NN * 128];
__device__ float    g_t [(size_t)NN * KDIM]; // t = h0 @ We
__device__ float    g_h1[(size_t)NN * KDIM]; // h1
// weights pre-split, transposed to [n][kpair]
__device__ unsigned g_wdh[256 * 128], g_wdl[256 * 128];
__device__ unsigned g_weh[256 * 128], g_wel[256 * 128];
__device__ unsigned g_wch[256 * 128], g_wcl[256 * 128];
__device__ float    g_bcat[256];
__device__ float g_deg[NN];
__device__ float g_dinv[NN];
__device__ int   g_cnt[NN];
__device__ int   g_rowptr[NN + 1];
__device__ int   g_cursor[NN];
__device__ int   g_src[EE];
__device__ float g_val[EE];
__device__ int   g_is64;

// ---------------- helpers ----------------
__device__ __forceinline__ void split_pair(float x0, float x1,
                                           unsigned& hi, unsigned& lo) {
    unsigned h;
    asm("cvt.rn.bf16x2.f32 %0, %1, %2;" : "=r"(h) : "f"(x1), "f"(x0));
    float h0 = __uint_as_float(h << 16);
    float h1 = __uint_as_float(h & 0xffff0000u);
    float r0 = x0 - h0, r1 = x1 - h1;
    unsigned l;
    asm("cvt.rn.bf16x2.f32 %0, %1, %2;" : "=r"(l) : "f"(r1), "f"(r0));
    hi = h; lo = l;
}

__device__ __forceinline__ uint32_t smem_u32(const void* p) {
    uint32_t a;
    asm("{ .reg .u64 t; cvta.to.shared.u64 t, %1; cvt.u32.u64 %0, t; }"
        : "=r"(a) : "l"(p));
    return a;
}

__device__ __forceinline__ void ldsm_x4(unsigned r[4], uint32_t addr) {
    asm volatile("ldmatrix.sync.aligned.m8n8.x4.shared.b16 {%0,%1,%2,%3}, [%4];"
        : "=r"(r[0]), "=r"(r[1]), "=r"(r[2]), "=r"(r[3]) : "r"(addr));
}

__device__ __forceinline__ void mma16(float c[4], const unsigned a[4],
                                      unsigned b0, unsigned b1) {
    asm volatile(
        "mma.sync.aligned.m16n8k16.row.col.f32.bf16.bf16.f32 "
        "{%0,%1,%2,%3}, {%4,%5,%6,%7}, {%8,%9}, {%0,%1,%2,%3};"
        : "+f"(c[0]), "+f"(c[1]), "+f"(c[2]), "+f"(c[3])
        : "r"(a[0]), "r"(a[1]), "r"(a[2]), "r"(a[3]), "r"(b0), "r"(b1));
}

__device__ __forceinline__ void cpa16(uint32_t dst, const void* src, int sz) {
    asm volatile("cp.async.cg.shared.global [%0], [%1], 16, %2;"
                 :: "r"(dst), "l"(src), "r"(sz) : "memory");
}
#define CPA_COMMIT() asm volatile("cp.async.commit_group;" ::: "memory")
#define CPA_WAIT1()  asm volatile("cp.async.wait_group 1;" ::: "memory")

// ---------------- edge-index dtype detection ----------------
__global__ void detect_kernel(const int* __restrict__ ei32, int n_int32) {
    __shared__ int any;
    if (threadIdx.x == 0) any = 0;
    __syncthreads();
    for (int i = threadIdx.x; i < 4096; i += blockDim.x) {
        int pos = 2 * i + 1;
        if (pos < n_int32 && ei32[pos] != 0) any = 1;
    }
    __syncthreads();
    if (threadIdx.x == 0) g_is64 = (any == 0) ? 1 : 0;
}

__device__ __forceinline__ int load_idx(const void* ei, int e, int part, int i) {
    if (g_is64) return (int)((const long long*)ei)[(size_t)part * e + i];
    return ((const int*)ei)[(size_t)part * e + i];
}

// ---------------- graph preprocessing ----------------
__global__ void init_kernel(int n) {
    int i = blockIdx.x * blockDim.x + threadIdx.x;
    if (i < n) { g_deg[i] = 1.0f; g_cnt[i] = 0; }
}

__global__ void edge_pass(const void* __restrict__ ei,
                          const float* __restrict__ ew, int e) {
    int i = blockIdx.x * blockDim.x + threadIdx.x;
    if (i >= e) return;
    int c = load_idx(ei, e, 1, i);
    if ((unsigned)c >= NN) return;
    atomicAdd(&g_deg[c], ew[i]);
    atomicAdd(&g_cnt[c], 1);
}

__global__ void dinv_kernel(int n) {
    int i = blockIdx.x * blockDim.x + threadIdx.x;
    if (i < n) g_dinv[i] = rsqrtf(g_deg[i]);
}

__global__ void scan_kernel(int n) {
    __shared__ int part[1024];
    int tid = threadIdx.x;
    int chunk = (n + 1023) >> 10;
    int beg = tid * chunk;
    int end = beg + chunk; if (end > n) end = n;
    int s = 0;
    for (int i = beg; i < end; i++) s += g_cnt[i];
    part[tid] = s;
    __syncthreads();
    for (int off = 1; off < 1024; off <<= 1) {
        int v = (tid >= off) ? part[tid - off] : 0;
        __syncthreads();
        part[tid] += v;
        __syncthreads();
    }
    int run = (tid > 0) ? part[tid - 1] : 0;
    for (int i = beg; i < end; i++) {
        g_rowptr[i] = run; g_cursor[i] = run; run += g_cnt[i];
    }
    if (tid == 1023) g_rowptr[n] = part[1023];
}

__global__ void scatter_kernel(const void* __restrict__ ei,
                               const float* __restrict__ ew, int e) {
    int i = blockIdx.x * blockDim.x + threadIdx.x;
    if (i >= e) return;
    int r = load_idx(ei, e, 0, i);
    int c = load_idx(ei, e, 1, i);
    if ((unsigned)r >= NN || (unsigned)c >= NN) return;
    int pos = atomicAdd(&g_cursor[c], 1);
    g_src[pos] = r;
    g_val[pos] = ew[i] * g_dinv[r];
}

// ---------------- split kernels ----------------
__global__ void split_x_kernel(const float* __restrict__ src) {
    int i = blockIdx.x * blockDim.x + threadIdx.x;   // quad (2 pairs)
    if (i >= NN * 64) return;
    float4 v = ((const float4*)src)[i];
    unsigned h0, l0, h1, l1;
    split_pair(v.x, v.y, h0, l0);
    split_pair(v.z, v.w, h1, l1);
    ((uint2*)g_ph)[i] = make_uint2(h0, h1);
    ((uint2*)g_pl)[i] = make_uint2(l0, l1);
}

template<int WSET>
__global__ void split_w_kernel(const float* __restrict__ w0, const float* __restrict__ w1,
                               const float* __restrict__ b0, const float* __restrict__ b1) {
    int i = blockIdx.x * blockDim.x + threadIdx.x;
    if (i >= 256 * 128) return;
    int n = i >> 7, j = i & 127;   // n-row, kpair
    float x0, x1;
    if (WSET == 2) {
        x0 = (n < 128) ? w0[(2 * j) * 128 + n]     : w1[(2 * j) * 128 + n - 128];
        x1 = (n < 128) ? w0[(2 * j + 1) * 128 + n] : w1[(2 * j + 1) * 128 + n - 128];
    } else {
        x0 = w0[(2 * j) * 256 + n];
        x1 = w0[(2 * j + 1) * 256 + n];
    }
    unsigned h, l;
    split_pair(x0, x1, h, l);
    if (WSET == 0) { g_wdh[i] = h; g_wdl[i] = l; }
    else if (WSET == 1) { g_weh[i] = h; g_wel[i] = l; }
    else { g_wch[i] = h; g_wcl[i] = l; }
    if (WSET == 2 && i < 256) g_bcat[i] = (i < 128) ? b0[i] : b1[i - 128];
}

// ---------------- 3-stage pipelined TC GEMM, wide-interleaved MMA schedule -------------
// Smem per matrix: [stage 3][plane 2][row 128][16B] = 12KB; 4 matrices = 48KB.
// MMA schedule per nt2: 3 waves x 4 independent accumulators (dep distance 4).
// MODE 0: A=P, W=wd, +bias +relu, split -> g_rh/g_rl
// MODE 1: A=R, W=we, f32 -> g_t
// MODE 2: A=P, W=wcat, +g_bcat, split halves -> Cout / Cout+NN*128
template<int MODE>
__global__ __launch_bounds__(256, 2)
void gemm_tc(const float* __restrict__ bias, float* __restrict__ Cout, int M) {
    const unsigned* Ah = (MODE == 1) ? g_rh : g_ph;
    const unsigned* Al = (MODE == 1) ? g_rl : g_pl;
    const unsigned* Wh = (MODE == 0) ? g_wdh : (MODE == 1) ? g_weh : g_wch;
    const unsigned* Wl = (MODE == 0) ? g_wdl : (MODE == 1) ? g_wel : g_wcl;

    __shared__ unsigned sAh[3 * 2 * 128 * 4];   // 12KB each
    __shared__ unsigned sAl[3 * 2 * 128 * 4];
    __shared__ unsigned sBh[3 * 2 * 128 * 4];
    __shared__ unsigned sBl[3 * 2 * 128 * 4];

    int tid  = threadIdx.x;
    int lane = tid & 31, wid = tid >> 5;
    int warp_m = wid & 3, warp_n = wid >> 2;
    int bm = blockIdx.y * 128;
    int bn = blockIdx.x * 128;
    int gid = lane >> 2, tig = lane & 3;

    uint32_t aH = smem_u32(sAh), aL = smem_u32(sAl);
    uint32_t bH = smem_u32(sBh), bL = smem_u32(sBl);

    // cp.async mapping: thread -> (row = tid&127, plane = tid>>7)
    int ld_row = tid & 127;
    int ld_plane = tid >> 7;
    int a_valid = (bm + ld_row < M) ? 16 : 0;
    uint32_t st_off = (uint32_t)(ld_plane * 2048 + ld_row * 16);
    size_t a_src_base = (size_t)(bm + ld_row) * 128 + ld_plane * 4;
    size_t b_src_base = (size_t)(bn + ld_row) * 128 + ld_plane * 4;

    // LDSM fragment addresses
    int lr = lane & 7;
    uint32_t a_frag = (uint32_t)((lane >> 4) * 2048
                    + (warp_m * 32 + lr + ((lane >> 3) & 1) * 8) * 16);
    uint32_t b_frag = (uint32_t)(((lane >> 3) & 1) * 2048
                    + (warp_n * 64 + lr + ((lane >> 4) ? 8 : 0)) * 16);

    float acc[2][8][4];
    #pragma unroll
    for (int a = 0; a < 2; a++)
        #pragma unroll
        for (int b = 0; b < 8; b++)
            #pragma unroll
            for (int c = 0; c < 4; c++) acc[a][b][c] = 0.f;

    // prologue: chunks 0,1 into stages 0,1
    #pragma unroll
    for (int s = 0; s < 2; s++) {
        uint32_t dst = st_off + s * 4096;
        size_t srcA = a_src_base + s * 8;
        size_t srcB = b_src_base + s * 8;
        cpa16(aH + dst, &Ah[srcA], a_valid);
        cpa16(aL + dst, &Al[srcA], a_valid);
        cpa16(bH + dst, &Wh[srcB], 16);
        cpa16(bL + dst, &Wl[srcB], 16);
        CPA_COMMIT();
    }

    int st_cur = 0;   // = ch % 3
    int st_wr  = 2;   // = (ch + 2) % 3
    for (int ch = 0; ch < 16; ch++) {          // 16 chunks of k16 (8 kpairs)
        CPA_WAIT1();
        __syncthreads();
        if (ch + 2 < 16) {
            uint32_t dst = st_off + (uint32_t)st_wr * 4096;
            size_t srcA = a_src_base + (ch + 2) * 8;
            size_t srcB = b_src_base + (ch + 2) * 8;
            cpa16(aH + dst, &Ah[srcA], a_valid);
            cpa16(aL + dst, &Al[srcA], a_valid);
            cpa16(bH + dst, &Wh[srcB], 16);
            cpa16(bL + dst, &Wl[srcB], 16);
        }
        CPA_COMMIT();                           // always commit (group accounting)

        uint32_t so = (uint32_t)st_cur * 4096;

        unsigned ah[2][4], al[2][4];
        #pragma unroll
        for (int mt = 0; mt < 2; mt++) {
            ldsm_x4(ah[mt], aH + so + a_frag + mt * 256);   // +16 rows
            ldsm_x4(al[mt], aL + so + a_frag + mt * 256);
        }
        #pragma unroll
        for (int nt2 = 0; nt2 < 4; nt2++) {
            unsigned bh4[4], bl4[4];
            ldsm_x4(bh4, bH + so + b_frag + nt2 * 256);
            ldsm_x4(bl4, bL + so + b_frag + nt2 * 256);
            // 4 independent accumulators; 3 waves, dep distance 4
            float* c0 = acc[0][2 * nt2];
            float* c1 = acc[0][2 * nt2 + 1];
            float* d0 = acc[1][2 * nt2];
            float* d1 = acc[1][2 * nt2 + 1];
            // wave 1: hi * lo
            mma16(c0, ah[0], bl4[0], bl4[1]);
            mma16(d0, ah[1], bl4[0], bl4[1]);
            mma16(c1, ah[0], bl4[2], bl4[3]);
            mma16(d1, ah[1], bl4[2], bl4[3]);
            // wave 2: lo * hi
            mma16(c0, al[0], bh4[0], bh4[1]);
            mma16(d0, al[1], bh4[0], bh4[1]);
            mma16(c1, al[0], bh4[2], bh4[3]);
            mma16(d1, al[1], bh4[2], bh4[3]);
            // wave 3: hi * hi
            mma16(c0, ah[0], bh4[0], bh4[1]);
            mma16(d0, ah[1], bh4[0], bh4[1]);
            mma16(c1, ah[0], bh4[2], bh4[3]);
            mma16(d1, ah[1], bh4[2], bh4[3]);
        }
        // advance stage counters (wrap mod 3)
        st_cur++; if (st_cur == 3) st_cur = 0;
        st_wr++;  if (st_wr == 3)  st_wr = 0;
    }
    __syncthreads();

    #pragma unroll
    for (int mt = 0; mt < 2; mt++) {
        int rr = bm + warp_m * 32 + mt * 16 + gid;
        #pragma unroll
        for (int nt = 0; nt < 8; nt++) {
            int c = bn + warp_n * 64 + nt * 8 + tig * 2;
            float v0 = acc[mt][nt][0], v1 = acc[mt][nt][1];
            float v2 = acc[mt][nt][2], v3 = acc[mt][nt][3];
            if (MODE != 1) {
                const float* bs = (MODE == 2) ? g_bcat : bias;
                float bb0 = bs[c], bb1 = bs[c + 1];
                v0 += bb0; v1 += bb1; v2 += bb0; v3 += bb1;
            }
            if (MODE == 0) {
                v0 = fmaxf(v0, 0.f); v1 = fmaxf(v1, 0.f);
                v2 = fmaxf(v2, 0.f); v3 = fmaxf(v3, 0.f);
                int cp = c >> 1;
                unsigned h, l;
                if (rr < M) {
                    split_pair(v0, v1, h, l);
                    g_rh[(size_t)rr * 128 + cp] = h; g_rl[(size_t)rr * 128 + cp] = l;
                }
                if (rr + 8 < M) {
                    split_pair(v2, v3, h, l);
                    g_rh[(size_t)(rr + 8) * 128 + cp] = h; g_rl[(size_t)(rr + 8) * 128 + cp] = l;
                }
            } else if (MODE == 1) {
                if (rr < M)     *(float2*)&g_t[(size_t)rr * 256 + c]       = make_float2(v0, v1);
                if (rr + 8 < M) *(float2*)&g_t[(size_t)(rr + 8) * 256 + c] = make_float2(v2, v3);
            } else {
                float* base = (c < 128) ? Cout : (Cout + (size_t)NN * 128);
                int cc = (c < 128) ? c : c - 128;
                if (rr < M)     *(float2*)&base[(size_t)rr * 128 + cc]       = make_float2(v0, v1);
                if (rr + 8 < M) *(float2*)&base[(size_t)(rr + 8) * 128 + cc] = make_float2(v2, v3);
            }
        }
    }
}

// ---------------- SpMM ----------------
template<int PHASE>
__global__ __launch_bounds__(256)
void spmm_kernel(const float* __restrict__ bias, int n) {
    const float* feat = (PHASE == 0) ? g_t : g_h1;
    int warp = (blockIdx.x * blockDim.x + threadIdx.x) >> 5;
    int lane = threadIdx.x & 31;
    if (warp >= n) return;
    int beg = g_rowptr[warp];
    int end = g_rowptr[warp + 1];
    const float4* f4 = (const float4*)feat;
    float4 acc0 = make_float4(0.f, 0.f, 0.f, 0.f);
    float4 acc1 = make_float4(0.f, 0.f, 0.f, 0.f);
    int e = beg;
    for (; e + 1 < end; e += 2) {
        int   r0 = g_src[e],     r1 = g_src[e + 1];
        float w0 = g_val[e],     w1 = g_val[e + 1];
        float4 a0 = f4[(size_t)r0 * 64 + lane];
        float4 b0 = f4[(size_t)r0 * 64 + 32 + lane];
        float4 a1 = f4[(size_t)r1 * 64 + lane];
        float4 b1 = f4[(size_t)r1 * 64 + 32 + lane];
        acc0.x = fmaf(w0, a0.x, acc0.x); acc0.y = fmaf(w0, a0.y, acc0.y);
        acc0.z = fmaf(w0, a0.z, acc0.z); acc0.w = fmaf(w0, a0.w, acc0.w);
        acc1.x = fmaf(w0, b0.x, acc1.x); acc1.y = fmaf(w0, b0.y, acc1.y);
        acc1.z = fmaf(w0, b0.z, acc1.z); acc1.w = fmaf(w0, b0.w, acc1.w);
        acc0.x = fmaf(w1, a1.x, acc0.x); acc0.y = fmaf(w1, a1.y, acc0.y);
        acc0.z = fmaf(w1, a1.z, acc0.z); acc0.w = fmaf(w1, a1.w, acc0.w);
        acc1.x = fmaf(w1, b1.x, acc1.x); acc1.y = fmaf(w1, b1.y, acc1.y);
        acc1.z = fmaf(w1, b1.z, acc1.z); acc1.w = fmaf(w1, b1.w, acc1.w);
    }
    if (e < end) {
        int   r = g_src[e];
        float v = g_val[e];
        float4 a = f4[(size_t)r * 64 + lane];
        float4 b = f4[(size_t)r * 64 + 32 + lane];
        acc0.x = fmaf(v, a.x, acc0.x); acc0.y = fmaf(v, a.y, acc0.y);
        acc0.z = fmaf(v, a.z, acc0.z); acc0.w = fmaf(v, a.w, acc0.w);
        acc1.x = fmaf(v, b.x, acc1.x); acc1.y = fmaf(v, b.y, acc1.y);
        acc1.z = fmaf(v, b.z, acc1.z); acc1.w = fmaf(v, b.w, acc1.w);
    }
    float di = g_dinv[warp];
    float d2 = di * di;
    float4 s0 = f4[(size_t)warp * 64 + lane];
    float4 s1 = f4[(size_t)warp * 64 + 32 + lane];
    float4 o0, o1;
    o0.x = di * acc0.x + d2 * s0.x; o0.y = di * acc0.y + d2 * s0.y;
    o0.z = di * acc0.z + d2 * s0.z; o0.w = di * acc0.w + d2 * s0.w;
    o1.x = di * acc1.x + d2 * s1.x; o1.y = di * acc1.y + d2 * s1.y;
    o1.z = di * acc1.z + d2 * s1.z; o1.w = di * acc1.w + d2 * s1.w;
    if (PHASE == 0) {
        const float4* b4 = (const float4*)bias;
        float4 c0 = b4[lane], c1 = b4[32 + lane];
        o0.x += c0.x; o0.y += c0.y; o0.z += c0.z; o0.w += c0.w;
        o1.x += c1.x; o1.y += c1.y; o1.z += c1.z; o1.w += c1.w;
        float4* out4 = (float4*)g_h1;
        out4[(size_t)warp * 64 + lane]      = o0;
        out4[(size_t)warp * 64 + 32 + lane] = o1;
    } else {
        unsigned h, l;
        size_t base = (size_t)warp * 128;
        split_pair(o0.x, o0.y, h, l); g_ph[base + 2 * lane] = h;      g_pl[base + 2 * lane] = l;
        split_pair(o0.z, o0.w, h, l); g_ph[base + 2 * lane + 1] = h;  g_pl[base + 2 * lane + 1] = l;
        split_pair(o1.x, o1.y, h, l); g_ph[base + 64 + 2 * lane] = h;     g_pl[base + 64 + 2 * lane] = l;
        split_pair(o1.z, o1.w, h, l); g_ph[base + 64 + 2 * lane + 1] = h; g_pl[base + 64 + 2 * lane + 1] = l;
    }
}

// ---------------- launch ----------------
extern "C" void kernel_launch(void* const* d_in, const int* in_sizes, int n_in,
                              void* d_out, int out_size) {
    const float* x  = (const float*)d_in[0];
    const void*  ei = d_in[1];
    const float* ew = (const float*)d_in[2];
    const float* wd = (const float*)d_in[3];
    const float* bd = (const float*)d_in[4];
    const float* we = (const float*)d_in[5];
    const float* be = (const float*)d_in[6];
    const float* wm = (const float*)d_in[7];
    const float* bmu = (const float*)d_in[8];
    const float* wl = (const float*)d_in[9];
    const float* bl = (const float*)d_in[10];
    float* out = (float*)d_out;

    const int n = NN;
    const int e = EE;

    dim3 grid(2, (n + 127) / 128);
    int spmm_blocks = (n * 32 + 255) / 256;

    // ordered so the first GEMM sits at launch index 3 (ncu capture slot)
    detect_kernel<<<1, 1024>>>((const int*)ei, 2 * e);                    // 0
    split_x_kernel<<<(NN * 64 + 255) / 256, 256>>>(x);                    // 1
    split_w_kernel<0><<<128, 256>>>(wd, nullptr, nullptr, nullptr);       // 2
    gemm_tc<0><<<grid, 256>>>(bd, nullptr, n);                            // 3: h0 -> R
    split_w_kernel<1><<<128, 256>>>(we, nullptr, nullptr, nullptr);       // 4
    gemm_tc<1><<<grid, 256>>>(nullptr, nullptr, n);                       // 5: t -> g_t
    split_w_kernel<2><<<128, 256>>>(wm, wl, bmu, bl);                     // 6
    init_kernel<<<(n + 255) / 256, 256>>>(n);                             // 7
    edge_pass<<<(e + 255) / 256, 256>>>(ei, ew, e);                       // 8
    dinv_kernel<<<(n + 255) / 256, 256>>>(n);                             // 9
    scan_kernel<<<1, 1024>>>(n);                                          // 10
    scatter_kernel<<<(e + 255) / 256, 256>>>(ei, ew, e);                  // 11
    spmm_kernel<0><<<spmm_blocks, 256>>>(be, n);                          // 12: h1
    spmm_kernel<1><<<spmm_blocks, 256>>>(nullptr, n);                     // 13: z -> P
    gemm_tc<2><<<grid, 256>>>(nullptr, out, n);                           // 14: mu/logstd
}

// round 13
// speedup vs baseline: 1.2568x; 1.1519x over previous
#include <cuda_runtime.h>
#include <cstdint>

#define NN   100000
#define EE   1600000
#define KDIM 256

// ---------------- scratch (device globals) ----------------
__device__ unsigned g_ph[(size_t)NN * 128];  // split A operand (x, later s) [row][kpair]
__device__ unsigned g_pl[(size_t)NN * 128];
__device__ float    g_t [(size_t)NN * KDIM]; // h0 (f32)
__device__ float    g_h1[(size_t)NN * KDIM]; // u = A@h0 (f32)
// weights pre-split, transposed to [n][kpair]
__device__ unsigned g_wdh[256 * 128], g_wdl[256 * 128];
__device__ unsigned g_w2h[256 * 128], g_w2l[256 * 128];
__device__ float    g_w2f[256 * 256];        // We @ Wcat (f32)
__device__ float    g_bvec[256];             // be^T @ Wcat
__device__ float    g_bc2[256];              // [bmu | bl]
__device__ float    g_a[NN];                 // rowsum of A_norm
__device__ float g_deg[NN];
__device__ float g_dinv[NN];
__device__ int   g_cnt[NN];
__device__ int   g_rowptr[NN + 1];
__device__ int   g_cursor[NN];
__device__ int   g_src[EE];
__device__ float g_val[EE];
__device__ int   g_is64;

// ---------------- helpers ----------------
__device__ __forceinline__ void split_pair(float x0, float x1,
                                           unsigned& hi, unsigned& lo) {
    unsigned h;
    asm("cvt.rn.bf16x2.f32 %0, %1, %2;" : "=r"(h) : "f"(x1), "f"(x0));
    float h0 = __uint_as_float(h << 16);
    float h1 = __uint_as_float(h & 0xffff0000u);
    float r0 = x0 - h0, r1 = x1 - h1;
    unsigned l;
    asm("cvt.rn.bf16x2.f32 %0, %1, %2;" : "=r"(l) : "f"(r1), "f"(r0));
    hi = h; lo = l;
}

__device__ __forceinline__ uint32_t smem_u32(const void* p) {
    uint32_t a;
    asm("{ .reg .u64 t; cvta.to.shared.u64 t, %1; cvt.u32.u64 %0, t; }"
        : "=r"(a) : "l"(p));
    return a;
}

__device__ __forceinline__ void ldsm_x4(unsigned r[4], uint32_t addr) {
    asm volatile("ldmatrix.sync.aligned.m8n8.x4.shared.b16 {%0,%1,%2,%3}, [%4];"
        : "=r"(r[0]), "=r"(r[1]), "=r"(r[2]), "=r"(r[3]) : "r"(addr));
}

__device__ __forceinline__ void mma16(float c[4], const unsigned a[4],
                                      unsigned b0, unsigned b1) {
    asm volatile(
        "mma.sync.aligned.m16n8k16.row.col.f32.bf16.bf16.f32 "
        "{%0,%1,%2,%3}, {%4,%5,%6,%7}, {%8,%9}, {%0,%1,%2,%3};"
        : "+f"(c[0]), "+f"(c[1]), "+f"(c[2]), "+f"(c[3])
        : "r"(a[0]), "r"(a[1]), "r"(a[2]), "r"(a[3]), "r"(b0), "r"(b1));
}

__device__ __forceinline__ void cpa16(uint32_t dst, const void* src, int sz) {
    asm volatile("cp.async.cg.shared.global [%0], [%1], 16, %2;"
                 :: "r"(dst), "l"(src), "r"(sz) : "memory");
}
#define CPA_COMMIT() asm volatile("cp.async.commit_group;" ::: "memory")
#define CPA_WAIT1()  asm volatile("cp.async.wait_group 1;" ::: "memory")

// ---------------- edge-index dtype detection ----------------
__global__ void detect_kernel(const int* __restrict__ ei32, int n_int32) {
    __shared__ int any;
    if (threadIdx.x == 0) any = 0;
    __syncthreads();
    for (int i = threadIdx.x; i < 4096; i += blockDim.x) {
        int pos = 2 * i + 1;
        if (pos < n_int32 && ei32[pos] != 0) any = 1;
    }
    __syncthreads();
    if (threadIdx.x == 0) g_is64 = (any == 0) ? 1 : 0;
}

__device__ __forceinline__ int load_idx(const void* ei, int e, int part, int i) {
    if (g_is64) return (int)((const long long*)ei)[(size_t)part * e + i];
    return ((const int*)ei)[(size_t)part * e + i];
}

// ---------------- graph preprocessing ----------------
__global__ void init_kernel(int n) {
    int i = blockIdx.x * blockDim.x + threadIdx.x;
    if (i < n) { g_deg[i] = 1.0f; g_cnt[i] = 0; }
}

__global__ void edge_pass(const void* __restrict__ ei,
                          const float* __restrict__ ew, int e) {
    int i = blockIdx.x * blockDim.x + threadIdx.x;
    if (i >= e) return;
    int c = load_idx(ei, e, 1, i);
    if ((unsigned)c >= NN) return;
    atomicAdd(&g_deg[c], ew[i]);
    atomicAdd(&g_cnt[c], 1);
}

__global__ void dinv_kernel(int n) {
    int i = blockIdx.x * blockDim.x + threadIdx.x;
    if (i < n) g_dinv[i] = rsqrtf(g_deg[i]);
}

__global__ void scan_kernel(int n) {
    __shared__ int part[1024];
    int tid = threadIdx.x;
    int chunk = (n + 1023) >> 10;
    int beg = tid * chunk;
    int end = beg + chunk; if (end > n) end = n;
    int s = 0;
    for (int i = beg; i < end; i++) s += g_cnt[i];
    part[tid] = s;
    __syncthreads();
    for (int off = 1; off < 1024; off <<= 1) {
        int v = (tid >= off) ? part[tid - off] : 0;
        __syncthreads();
        part[tid] += v;
        __syncthreads();
    }
    int run = (tid > 0) ? part[tid - 1] : 0;
    for (int i = beg; i < end; i++) {
        g_rowptr[i] = run; g_cursor[i] = run; run += g_cnt[i];
    }
    if (tid == 1023) g_rowptr[n] = part[1023];
}

__global__ void scatter_kernel(const void* __restrict__ ei,
                               const float* __restrict__ ew, int e) {
    int i = blockIdx.x * blockDim.x + threadIdx.x;
    if (i >= e) return;
    int r = load_idx(ei, e, 0, i);
    int c = load_idx(ei, e, 1, i);
    if ((unsigned)r >= NN || (unsigned)c >= NN) return;
    int pos = atomicAdd(&g_cursor[c], 1);
    g_src[pos] = r;
    g_val[pos] = ew[i] * g_dinv[r];
}

// a = A_norm @ 1  (per-dest rowsum incl. self loop)
__global__ void rowsum_kernel(int n) {
    int i = blockIdx.x * blockDim.x + threadIdx.x;
    if (i >= n) return;
    float s = 0.f;
    int beg = g_rowptr[i], end = g_rowptr[i + 1];
    for (int e = beg; e < end; e++) s += g_val[e];
    float di = g_dinv[i];
    g_a[i] = di * s + di * di;
}

// ---------------- composed-weight kernels ----------------
// wcat(j,n) helper: columns 0-127 from wm, 128-255 from wl
// w2[k][n] = sum_j We[k][j] * wcat[j][n]
__global__ void w2_kernel(const float* __restrict__ we,
                          const float* __restrict__ wm,
                          const float* __restrict__ wl) {
    int idx = blockIdx.x * blockDim.x + threadIdx.x;
    if (idx >= 256 * 256) return;
    int k = idx >> 8, n = idx & 255;
    float s = 0.f;
    if (n < 128) {
        for (int j = 0; j < 256; j++) s = fmaf(we[k * 256 + j], wm[j * 128 + n], s);
    } else {
        int nn = n - 128;
        for (int j = 0; j < 256; j++) s = fmaf(we[k * 256 + j], wl[j * 128 + nn], s);
    }
    g_w2f[idx] = s;
}

// bvec[n] = sum_k be[k] * wcat[k][n];  bc2[n] = bcat[n]
__global__ void bvec_kernel(const float* __restrict__ be,
                            const float* __restrict__ wm,
                            const float* __restrict__ wl,
                            const float* __restrict__ bmu,
                            const float* __restrict__ bl) {
    int n = blockIdx.x * blockDim.x + threadIdx.x;
    if (n >= 256) return;
    float s = 0.f;
    if (n < 128) {
        for (int k = 0; k < 256; k++) s = fmaf(be[k], wm[k * 128 + n], s);
        g_bc2[n] = bmu[n];
    } else {
        int nn = n - 128;
        for (int k = 0; k < 256; k++) s = fmaf(be[k], wl[k * 128 + nn], s);
        g_bc2[n] = bl[nn];
    }
    g_bvec[n] = s;
}

// ---------------- split kernels ----------------
__global__ void split_x_kernel(const float* __restrict__ src) {
    int i = blockIdx.x * blockDim.x + threadIdx.x;   // quad (2 pairs)
    if (i >= NN * 64) return;
    float4 v = ((const float4*)src)[i];
    unsigned h0, l0, h1, l1;
    split_pair(v.x, v.y, h0, l0);
    split_pair(v.z, v.w, h1, l1);
    ((uint2*)g_ph)[i] = make_uint2(h0, h1);
    ((uint2*)g_pl)[i] = make_uint2(l0, l1);
}

// W[256k][256n] (f32, k-major rows) -> transposed split [n][kpair]
template<int WSET>
__global__ void split_w_kernel(const float* __restrict__ w0) {
    int i = blockIdx.x * blockDim.x + threadIdx.x;
    if (i >= 256 * 128) return;
    int n = i >> 7, j = i & 127;   // n-row, kpair
    float x0 = w0[(2 * j) * 256 + n];
    float x1 = w0[(2 * j + 1) * 256 + n];
    unsigned h, l;
    split_pair(x0, x1, h, l);
    if (WSET == 0) { g_wdh[i] = h; g_wdl[i] = l; }
    else           { g_w2h[i] = h; g_w2l[i] = l; }
}

// ---------------- 3-stage pipelined TC GEMM (cp.async, LDSM, pre-split) -------------
// MODE 0: A=P(x), W=wd split, +bias +relu, f32 -> g_t
// MODE 2: A=P(s), W=w2 split, epilogue v += a[r]*bvec[c] + bc2[c], split halves -> Cout
template<int MODE>
__global__ __launch_bounds__(256, 2)
void gemm_tc(const float* __restrict__ bias, float* __restrict__ Cout, int M) {
    const unsigned* Ah = g_ph;
    const unsigned* Al = g_pl;
    const unsigned* Wh = (MODE == 0) ? g_wdh : g_w2h;
    const unsigned* Wl = (MODE == 0) ? g_wdl : g_w2l;

    __shared__ unsigned sAh[3 * 2 * 128 * 4];   // 12KB each
    __shared__ unsigned sAl[3 * 2 * 128 * 4];
    __shared__ unsigned sBh[3 * 2 * 128 * 4];
    __shared__ unsigned sBl[3 * 2 * 128 * 4];

    int tid  = threadIdx.x;
    int lane = tid & 31, wid = tid >> 5;
    int warp_m = wid & 3, warp_n = wid >> 2;
    int bm = blockIdx.y * 128;
    int bn = blockIdx.x * 128;
    int gid = lane >> 2, tig = lane & 3;

    uint32_t aH = smem_u32(sAh), aL = smem_u32(sAl);
    uint32_t bH = smem_u32(sBh), bL = smem_u32(sBl);

    int ld_row = tid & 127;
    int ld_plane = tid >> 7;
    int a_valid = (bm + ld_row < M) ? 16 : 0;
    uint32_t st_off = (uint32_t)(ld_plane * 2048 + ld_row * 16);
    size_t a_src_base = (size_t)(bm + ld_row) * 128 + ld_plane * 4;
    size_t b_src_base = (size_t)(bn + ld_row) * 128 + ld_plane * 4;

    int lr = lane & 7;
    uint32_t a_frag = (uint32_t)((lane >> 4) * 2048
                    + (warp_m * 32 + lr + ((lane >> 3) & 1) * 8) * 16);
    uint32_t b_frag = (uint32_t)(((lane >> 3) & 1) * 2048
                    + (warp_n * 64 + lr + ((lane >> 4) ? 8 : 0)) * 16);

    float acc[2][8][4];
    #pragma unroll
    for (int a = 0; a < 2; a++)
        #pragma unroll
        for (int b = 0; b < 8; b++)
            #pragma unroll
            for (int c = 0; c < 4; c++) acc[a][b][c] = 0.f;

    #pragma unroll
    for (int s = 0; s < 2; s++) {
        uint32_t dst = st_off + s * 4096;
        size_t srcA = a_src_base + s * 8;
        size_t srcB = b_src_base + s * 8;
        cpa16(aH + dst, &Ah[srcA], a_valid);
        cpa16(aL + dst, &Al[srcA], a_valid);
        cpa16(bH + dst, &Wh[srcB], 16);
        cpa16(bL + dst, &Wl[srcB], 16);
        CPA_COMMIT();
    }

    int st_cur = 0;
    int st_wr  = 2;
    for (int ch = 0; ch < 16; ch++) {
        CPA_WAIT1();
        __syncthreads();
        if (ch + 2 < 16) {
            uint32_t dst = st_off + (uint32_t)st_wr * 4096;
            size_t srcA = a_src_base + (ch + 2) * 8;
            size_t srcB = b_src_base + (ch + 2) * 8;
            cpa16(aH + dst, &Ah[srcA], a_valid);
            cpa16(aL + dst, &Al[srcA], a_valid);
            cpa16(bH + dst, &Wh[srcB], 16);
            cpa16(bL + dst, &Wl[srcB], 16);
        }
        CPA_COMMIT();

        uint32_t so = (uint32_t)st_cur * 4096;

        unsigned ah[2][4], al[2][4];
        #pragma unroll
        for (int mt = 0; mt < 2; mt++) {
            ldsm_x4(ah[mt], aH + so + a_frag + mt * 256);
            ldsm_x4(al[mt], aL + so + a_frag + mt * 256);
        }
        #pragma unroll
        for (int nt2 = 0; nt2 < 4; nt2++) {
            unsigned bh4[4], bl4[4];
            ldsm_x4(bh4, bH + so + b_frag + nt2 * 256);
            ldsm_x4(bl4, bL + so + b_frag + nt2 * 256);
            float* c0 = acc[0][2 * nt2];
            float* c1 = acc[0][2 * nt2 + 1];
            float* d0 = acc[1][2 * nt2];
            float* d1 = acc[1][2 * nt2 + 1];
            mma16(c0, ah[0], bl4[0], bl4[1]);
            mma16(d0, ah[1], bl4[0], bl4[1]);
            mma16(c1, ah[0], bl4[2], bl4[3]);
            mma16(d1, ah[1], bl4[2], bl4[3]);
            mma16(c0, al[0], bh4[0], bh4[1]);
            mma16(d0, al[1], bh4[0], bh4[1]);
            mma16(c1, al[0], bh4[2], bh4[3]);
            mma16(d1, al[1], bh4[2], bh4[3]);
            mma16(c0, ah[0], bh4[0], bh4[1]);
            mma16(d0, ah[1], bh4[0], bh4[1]);
            mma16(c1, ah[0], bh4[2], bh4[3]);
            mma16(d1, ah[1], bh4[2], bh4[3]);
        }
        st_cur++; if (st_cur == 3) st_cur = 0;
        st_wr++;  if (st_wr == 3)  st_wr = 0;
    }
    __syncthreads();

    #pragma unroll
    for (int mt = 0; mt < 2; mt++) {
        int rr = bm + warp_m * 32 + mt * 16 + gid;
        float a_r0 = 0.f, a_r8 = 0.f;
        if (MODE == 2) {
            if (rr < M)     a_r0 = g_a[rr];
            if (rr + 8 < M) a_r8 = g_a[rr + 8];
        }
        #pragma unroll
        for (int nt = 0; nt < 8; nt++) {
            int c = bn + warp_n * 64 + nt * 8 + tig * 2;
            float v0 = acc[mt][nt][0], v1 = acc[mt][nt][1];
            float v2 = acc[mt][nt][2], v3 = acc[mt][nt][3];
            if (MODE == 0) {
                float bb0 = bias[c], bb1 = bias[c + 1];
                v0 = fmaxf(v0 + bb0, 0.f); v1 = fmaxf(v1 + bb1, 0.f);
                v2 = fmaxf(v2 + bb0, 0.f); v3 = fmaxf(v3 + bb1, 0.f);
                if (rr < M)     *(float2*)&g_t[(size_t)rr * 256 + c]       = make_float2(v0, v1);
                if (rr + 8 < M) *(float2*)&g_t[(size_t)(rr + 8) * 256 + c] = make_float2(v2, v3);
            } else {
                float bv0 = g_bvec[c], bv1 = g_bvec[c + 1];
                float bc0 = g_bc2[c],  bc1 = g_bc2[c + 1];
                v0 += a_r0 * bv0 + bc0; v1 += a_r0 * bv1 + bc1;
                v2 += a_r8 * bv0 + bc0; v3 += a_r8 * bv1 + bc1;
                float* base = (c < 128) ? Cout : (Cout + (size_t)NN * 128);
                int cc = (c < 128) ? c : c - 128;
                if (rr < M)     *(float2*)&base[(size_t)rr * 128 + cc]       = make_float2(v0, v1);
                if (rr + 8 < M) *(float2*)&base[(size_t)(rr + 8) * 128 + cc] = make_float2(v2, v3);
            }
        }
    }
}

// ---------------- SpMM ----------------
// PHASE 0: g_t (h0) -> g_h1 (f32, no bias).  PHASE 1: g_h1 -> split s into P.
template<int PHASE>
__global__ __launch_bounds__(256)
void spmm_kernel(int n) {
    const float* feat = (PHASE == 0) ? g_t : g_h1;
    int warp = (blockIdx.x * blockDim.x + threadIdx.x) >> 5;
    int lane = threadIdx.x & 31;
    if (warp >= n) return;
    int beg = g_rowptr[warp];
    int end = g_rowptr[warp + 1];
    const float4* f4 = (const float4*)feat;
    float4 acc0 = make_float4(0.f, 0.f, 0.f, 0.f);
    float4 acc1 = make_float4(0.f, 0.f, 0.f, 0.f);
    int e = beg;
    for (; e + 1 < end; e += 2) {
        int   r0 = g_src[e],     r1 = g_src[e + 1];
        float w0 = g_val[e],     w1 = g_val[e + 1];
        float4 a0 = f4[(size_t)r0 * 64 + lane];
        float4 b0 = f4[(size_t)r0 * 64 + 32 + lane];
        float4 a1 = f4[(size_t)r1 * 64 + lane];
        float4 b1 = f4[(size_t)r1 * 64 + 32 + lane];
        acc0.x = fmaf(w0, a0.x, acc0.x); acc0.y = fmaf(w0, a0.y, acc0.y);
        acc0.z = fmaf(w0, a0.z, acc0.z); acc0.w = fmaf(w0, a0.w, acc0.w);
        acc1.x = fmaf(w0, b0.x, acc1.x); acc1.y = fmaf(w0, b0.y, acc1.y);
        acc1.z = fmaf(w0, b0.z, acc1.z); acc1.w = fmaf(w0, b0.w, acc1.w);
        acc0.x = fmaf(w1, a1.x, acc0.x); acc0.y = fmaf(w1, a1.y, acc0.y);
        acc0.z = fmaf(w1, a1.z, acc0.z); acc0.w = fmaf(w1, a1.w, acc0.w);
        acc1.x = fmaf(w1, b1.x, acc1.x); acc1.y = fmaf(w1, b1.y, acc1.y);
        acc1.z = fmaf(w1, b1.z, acc1.z); acc1.w = fmaf(w1, b1.w, acc1.w);
    }
    if (e < end) {
        int   r = g_src[e];
        float v = g_val[e];
        float4 a = f4[(size_t)r * 64 + lane];
        float4 b = f4[(size_t)r * 64 + 32 + lane];
        acc0.x = fmaf(v, a.x, acc0.x); acc0.y = fmaf(v, a.y, acc0.y);
        acc0.z = fmaf(v, a.z, acc0.z); acc0.w = fmaf(v, a.w, acc0.w);
        acc1.x = fmaf(v, b.x, acc1.x); acc1.y = fmaf(v, b.y, acc1.y);
        acc1.z = fmaf(v, b.z, acc1.z); acc1.w = fmaf(v, b.w, acc1.w);
    }
    float di = g_dinv[warp];
    float d2 = di * di;
    float4 s0 = f4[(size_t)warp * 64 + lane];
    float4 s1 = f4[(size_t)warp * 64 + 32 + lane];
    float4 o0, o1;
    o0.x = di * acc0.x + d2 * s0.x; o0.y = di * acc0.y + d2 * s0.y;
    o0.z = di * acc0.z + d2 * s0.z; o0.w = di * acc0.w + d2 * s0.w;
    o1.x = di * acc1.x + d2 * s1.x; o1.y = di * acc1.y + d2 * s1.y;
    o1.z = di * acc1.z + d2 * s1.z; o1.w = di * acc1.w + d2 * s1.w;
    if (PHASE == 0) {
        float4* out4 = (float4*)g_h1;
        out4[(size_t)warp * 64 + lane]      = o0;
        out4[(size_t)warp * 64 + 32 + lane] = o1;
    } else {
        unsigned h, l;
        size_t base = (size_t)warp * 128;
        split_pair(o0.x, o0.y, h, l); g_ph[base + 2 * lane] = h;      g_pl[base + 2 * lane] = l;
        split_pair(o0.z, o0.w, h, l); g_ph[base + 2 * lane + 1] = h;  g_pl[base + 2 * lane + 1] = l;
        split_pair(o1.x, o1.y, h, l); g_ph[base + 64 + 2 * lane] = h;     g_pl[base + 64 + 2 * lane] = l;
        split_pair(o1.z, o1.w, h, l); g_ph[base + 64 + 2 * lane + 1] = h; g_pl[base + 64 + 2 * lane + 1] = l;
    }
}

// ---------------- launch ----------------
extern "C" void kernel_launch(void* const* d_in, const int* in_sizes, int n_in,
                              void* d_out, int out_size) {
    const float* x  = (const float*)d_in[0];
    const void*  ei = d_in[1];
    const float* ew = (const float*)d_in[2];
    const float* wd = (const float*)d_in[3];
    const float* bd = (const float*)d_in[4];
    const float* we = (const float*)d_in[5];
    const float* be = (const float*)d_in[6];
    const float* wm = (const float*)d_in[7];
    const float* bmu = (const float*)d_in[8];
    const float* wl = (const float*)d_in[9];
    const float* bl = (const float*)d_in[10];
    float* out = (float*)d_out;

    const int n = NN;
    const int e = EE;

    dim3 grid(2, (n + 127) / 128);
    int spmm_blocks = (n * 32 + 255) / 256;

    // first GEMM pinned at launch index 3 for the ncu capture slot
    detect_kernel<<<1, 1024>>>((const int*)ei, 2 * e);                    // 0
    split_x_kernel<<<(NN * 64 + 255) / 256, 256>>>(x);                    // 1
    split_w_kernel<0><<<128, 256>>>(wd);                                  // 2
    gemm_tc<0><<<grid, 256>>>(bd, nullptr, n);                            // 3: h0 -> g_t
    // composed weights + biases
    float* w2f_dummy = nullptr; (void)w2f_dummy;
    w2_kernel<<<256, 256>>>(we, wm, wl);                                  // 4
    bvec_kernel<<<1, 256>>>(be, wm, wl, bmu, bl);                         // 5
    // split_w<1> reads g_w2f directly via device symbol: pass pointer through a launch arg
    // (g_w2f is a device global; we need its address kernel-side — use a small shim)
    // Implemented: split_w2_kernel below reads g_w2f directly.
    // graph prep
    init_kernel<<<(n + 255) / 256, 256>>>(n);                             // 6
    edge_pass<<<(e + 255) / 256, 256>>>(ei, ew, e);                       // 7
    dinv_kernel<<<(n + 255) / 256, 256>>>(n);                             // 8
    scan_kernel<<<1, 1024>>>(n);                                          // 9
    scatter_kernel<<<(e + 255) / 256, 256>>>(ei, ew, e);                  // 10
    rowsum_kernel<<<(n + 255) / 256, 256>>>(n);                           // 11
    // split composed weight (reads g_w2f device global)
    extern __global__ void split_w2_kernel();
    split_w2_kernel<<<128, 256>>>();                                      // 12
    spmm_kernel<0><<<spmm_blocks, 256>>>(n);                              // 13: u = A@h0
    spmm_kernel<1><<<spmm_blocks, 256>>>(n);                              // 14: s = A@u -> split P
    gemm_tc<2><<<grid, 256>>>(nullptr, out, n);                           // 15: out
}

// split composed weight g_w2f [256k][256n] -> g_w2h/g_w2l [n][kpair]
__global__ void split_w2_kernel() {
    int i = blockIdx.x * blockDim.x + threadIdx.x;
    if (i >= 256 * 128) return;
    int n = i >> 7, j = i & 127;
    float x0 = g_w2f[(2 * j) * 256 + n];
    float x1 = g_w2f[(2 * j + 1) * 256 + n];
    unsigned h, l;
    split_pair(x0, x1, h, l);
    g_w2h[i] = h; g_w2l[i] = l;
}

// round 14
// speedup vs baseline: 1.2784x; 1.0171x over previous
#include <cuda_runtime.h>
#include <cstdint>

#define NN   100000
#define EE   1600000
#define KDIM 256

// ---------------- scratch (device globals) ----------------
__device__ unsigned g_ph[(size_t)NN * 128];  // split A operand (x, later s) [row][kpair]
__device__ unsigned g_pl[(size_t)NN * 128];
__device__ float    g_t [(size_t)NN * KDIM]; // h0 (f32)
__device__ float    g_h1[(size_t)NN * KDIM]; // u = A@h0 (f32)
__device__ unsigned g_wdh[256 * 128], g_wdl[256 * 128];
__device__ unsigned g_w2h[256 * 128], g_w2l[256 * 128];
__device__ float    g_w2f[256 * 256];        // We @ Wcat
__device__ float    g_bvec[256];             // be^T @ Wcat
__device__ float    g_bc2[256];              // [bmu | bl]
__device__ float    g_a[NN];                 // rowsum of A_norm
__device__ float g_deg[NN];
__device__ float g_dinv[NN];
__device__ int   g_cnt[NN];
__device__ int   g_rowptr[NN + 1];
__device__ int   g_cursor[NN];
__device__ int   g_src[EE];
__device__ float g_val[EE];
__device__ int   g_is64;

// ---------------- helpers ----------------
__device__ __forceinline__ void split_pair(float x0, float x1,
                                           unsigned& hi, unsigned& lo) {
    unsigned h;
    asm("cvt.rn.bf16x2.f32 %0, %1, %2;" : "=r"(h) : "f"(x1), "f"(x0));
    float h0 = __uint_as_float(h << 16);
    float h1 = __uint_as_float(h & 0xffff0000u);
    float r0 = x0 - h0, r1 = x1 - h1;
    unsigned l;
    asm("cvt.rn.bf16x2.f32 %0, %1, %2;" : "=r"(l) : "f"(r1), "f"(r0));
    hi = h; lo = l;
}

__device__ __forceinline__ uint32_t smem_u32(const void* p) {
    uint32_t a;
    asm("{ .reg .u64 t; cvta.to.shared.u64 t, %1; cvt.u32.u64 %0, t; }"
        : "=r"(a) : "l"(p));
    return a;
}

__device__ __forceinline__ void ldsm_x4(unsigned r[4], uint32_t addr) {
    asm volatile("ldmatrix.sync.aligned.m8n8.x4.shared.b16 {%0,%1,%2,%3}, [%4];"
        : "=r"(r[0]), "=r"(r[1]), "=r"(r[2]), "=r"(r[3]) : "r"(addr));
}

__device__ __forceinline__ void mma16(float c[4], const unsigned a[4],
                                      unsigned b0, unsigned b1) {
    asm volatile(
        "mma.sync.aligned.m16n8k16.row.col.f32.bf16.bf16.f32 "
        "{%0,%1,%2,%3}, {%4,%5,%6,%7}, {%8,%9}, {%0,%1,%2,%3};"
        : "+f"(c[0]), "+f"(c[1]), "+f"(c[2]), "+f"(c[3])
        : "r"(a[0]), "r"(a[1]), "r"(a[2]), "r"(a[3]), "r"(b0), "r"(b1));
}

__device__ __forceinline__ void cpa16(uint32_t dst, const void* src, int sz) {
    asm volatile("cp.async.cg.shared.global [%0], [%1], 16, %2;"
                 :: "r"(dst), "l"(src), "r"(sz) : "memory");
}
#define CPA_COMMIT() asm volatile("cp.async.commit_group;" ::: "memory")
#define CPA_WAIT1()  asm volatile("cp.async.wait_group 1;" ::: "memory")

// ---------------- edge-index dtype detection ----------------
__global__ void detect_kernel(const int* __restrict__ ei32, int n_int32) {
    __shared__ int any;
    if (threadIdx.x == 0) any = 0;
    __syncthreads();
    for (int i = threadIdx.x; i < 4096; i += blockDim.x) {
        int pos = 2 * i + 1;
        if (pos < n_int32 && ei32[pos] != 0) any = 1;
    }
    __syncthreads();
    if (threadIdx.x == 0) g_is64 = (any == 0) ? 1 : 0;
}

__device__ __forceinline__ int load_idx(const void* ei, int e, int part, int i) {
    if (g_is64) return (int)((const long long*)ei)[(size_t)part * e + i];
    return ((const int*)ei)[(size_t)part * e + i];
}

// ---------------- graph preprocessing ----------------
__global__ void init_kernel(int n) {
    int i = blockIdx.x * blockDim.x + threadIdx.x;
    if (i < n) { g_deg[i] = 1.0f; g_cnt[i] = 0; }
}

__global__ void edge_pass(const void* __restrict__ ei,
                          const float* __restrict__ ew, int e) {
    int i = blockIdx.x * blockDim.x + threadIdx.x;
    if (i >= e) return;
    int c = load_idx(ei, e, 1, i);
    if ((unsigned)c >= NN) return;
    atomicAdd(&g_deg[c], ew[i]);
    atomicAdd(&g_cnt[c], 1);
}

__global__ void dinv_kernel(int n) {
    int i = blockIdx.x * blockDim.x + threadIdx.x;
    if (i < n) g_dinv[i] = rsqrtf(g_deg[i]);
}

__global__ void scan_kernel(int n) {
    __shared__ int part[1024];
    int tid = threadIdx.x;
    int chunk = (n + 1023) >> 10;
    int beg = tid * chunk;
    int end = beg + chunk; if (end > n) end = n;
    int s = 0;
    for (int i = beg; i < end; i++) s += g_cnt[i];
    part[tid] = s;
    __syncthreads();
    for (int off = 1; off < 1024; off <<= 1) {
        int v = (tid >= off) ? part[tid - off] : 0;
        __syncthreads();
        part[tid] += v;
        __syncthreads();
    }
    int run = (tid > 0) ? part[tid - 1] : 0;
    for (int i = beg; i < end; i++) {
        g_rowptr[i] = run; g_cursor[i] = run; run += g_cnt[i];
    }
    if (tid == 1023) g_rowptr[n] = part[1023];
}

__global__ void scatter_kernel(const void* __restrict__ ei,
                               const float* __restrict__ ew, int e) {
    int i = blockIdx.x * blockDim.x + threadIdx.x;
    if (i >= e) return;
    int r = load_idx(ei, e, 0, i);
    int c = load_idx(ei, e, 1, i);
    if ((unsigned)r >= NN || (unsigned)c >= NN) return;
    int pos = atomicAdd(&g_cursor[c], 1);
    g_src[pos] = r;
    g_val[pos] = ew[i] * g_dinv[r];
}

// a = A_norm @ 1
__global__ void rowsum_kernel(int n) {
    int i = blockIdx.x * blockDim.x + threadIdx.x;
    if (i >= n) return;
    float s = 0.f;
    int beg = g_rowptr[i], end = g_rowptr[i + 1];
    for (int e = beg; e < end; e++) s += g_val[e];
    float di = g_dinv[i];
    g_a[i] = di * s + di * di;
}

// ---------------- composed-weight kernels ----------------
__global__ void w2_kernel(const float* __restrict__ we,
                          const float* __restrict__ wm,
                          const float* __restrict__ wl) {
    int idx = blockIdx.x * blockDim.x + threadIdx.x;
    if (idx >= 256 * 256) return;
    int k = idx >> 8, n = idx & 255;
    float s = 0.f;
    if (n < 128) {
        for (int j = 0; j < 256; j++) s = fmaf(we[k * 256 + j], wm[j * 128 + n], s);
    } else {
        int nn = n - 128;
        for (int j = 0; j < 256; j++) s = fmaf(we[k * 256 + j], wl[j * 128 + nn], s);
    }
    g_w2f[idx] = s;
}

__global__ void bvec_kernel(const float* __restrict__ be,
                            const float* __restrict__ wm,
                            const float* __restrict__ wl,
                            const float* __restrict__ bmu,
                            const float* __restrict__ bl) {
    int n = blockIdx.x * blockDim.x + threadIdx.x;
    if (n >= 256) return;
    float s = 0.f;
    if (n < 128) {
        for (int k = 0; k < 256; k++) s = fmaf(be[k], wm[k * 128 + n], s);
        g_bc2[n] = bmu[n];
    } else {
        int nn = n - 128;
        for (int k = 0; k < 256; k++) s = fmaf(be[k], wl[k * 128 + nn], s);
        g_bc2[n] = bl[nn];
    }
    g_bvec[n] = s;
}

// ---------------- split kernels ----------------
__global__ void split_x_kernel(const float* __restrict__ src) {
    int i = blockIdx.x * blockDim.x + threadIdx.x;
    if (i >= NN * 64) return;
    float4 v = ((const float4*)src)[i];
    unsigned h0, l0, h1, l1;
    split_pair(v.x, v.y, h0, l0);
    split_pair(v.z, v.w, h1, l1);
    ((uint2*)g_ph)[i] = make_uint2(h0, h1);
    ((uint2*)g_pl)[i] = make_uint2(l0, l1);
}

__global__ void split_wd_kernel(const float* __restrict__ w0) {
    int i = blockIdx.x * blockDim.x + threadIdx.x;
    if (i >= 256 * 128) return;
    int n = i >> 7, j = i & 127;
    unsigned h, l;
    split_pair(w0[(2 * j) * 256 + n], w0[(2 * j + 1) * 256 + n], h, l);
    g_wdh[i] = h; g_wdl[i] = l;
}

__global__ void split_w2_kernel() {
    int i = blockIdx.x * blockDim.x + threadIdx.x;
    if (i >= 256 * 128) return;
    int n = i >> 7, j = i & 127;
    unsigned h, l;
    split_pair(g_w2f[(2 * j) * 256 + n], g_w2f[(2 * j + 1) * 256 + n], h, l);
    g_w2h[i] = h; g_w2l[i] = l;
}

// ---------------- 3-stage pipelined TC GEMM, 128x64 tile, 3 CTAs/SM -------------
// Smem: A [stage3][plane2][row128][16B]=12KB x2(hi/lo), B [stage3][plane2][row64][16B]=6KB x2 -> 36KB.
// MODE 0: A=P(x), W=wd split, +bias +relu, f32 -> g_t
// MODE 2: A=P(s), W=w2 split, epilogue v += a[r]*bvec[c] + bc2[c], split halves -> Cout
template<int MODE>
__global__ __launch_bounds__(256, 3)
void gemm_tc(const float* __restrict__ bias, float* __restrict__ Cout, int M) {
    const unsigned* Ah = g_ph;
    const unsigned* Al = g_pl;
    const unsigned* Wh = (MODE == 0) ? g_wdh : g_w2h;
    const unsigned* Wl = (MODE == 0) ? g_wdl : g_w2l;

    __shared__ unsigned sAh[3 * 2 * 128 * 4];   // 12KB
    __shared__ unsigned sAl[3 * 2 * 128 * 4];   // 12KB
    __shared__ unsigned sBh[3 * 2 * 64 * 4];    // 6KB
    __shared__ unsigned sBl[3 * 2 * 64 * 4];    // 6KB

    int tid  = threadIdx.x;
    int lane = tid & 31, wid = tid >> 5;
    int warp_m = wid & 3, warp_n = wid >> 2;    // 4 x 2 warps: 32 rows x 32 cols each
    int bm = blockIdx.y * 128;
    int bn = blockIdx.x * 64;
    int gid = lane >> 2, tig = lane & 3;

    uint32_t aH = smem_u32(sAh), aL = smem_u32(sAl);
    uint32_t bH = smem_u32(sBh), bL = smem_u32(sBl);

    // cp.async A mapping: all threads (row = tid&127, plane = tid>>7)
    int ld_row = tid & 127;
    int ld_plane = tid >> 7;
    int a_valid = (bm + ld_row < M) ? 16 : 0;
    uint32_t a_st = (uint32_t)(ld_plane * 2048 + ld_row * 16);
    size_t a_src_base = (size_t)(bm + ld_row) * 128 + ld_plane * 4;
    // cp.async B mapping: threads < 128 (row = tid&63, plane = (tid>>6)&1)
    int b_row = tid & 63;
    int b_plane = (tid >> 6) & 1;
    uint32_t b_st = (uint32_t)(b_plane * 1024 + b_row * 16);
    size_t b_src_base = (size_t)(bn + b_row) * 128 + b_plane * 4;
    bool do_b = (tid < 128);

    // LDSM fragment addresses
    int lr = lane & 7;
    uint32_t a_frag = (uint32_t)((lane >> 4) * 2048
                    + (warp_m * 32 + lr + ((lane >> 3) & 1) * 8) * 16);
    uint32_t b_frag = (uint32_t)(((lane >> 3) & 1) * 1024
                    + (warp_n * 32 + lr + ((lane >> 4) ? 8 : 0)) * 16);

    float acc[2][4][4];
    #pragma unroll
    for (int a = 0; a < 2; a++)
        #pragma unroll
        for (int b = 0; b < 4; b++)
            #pragma unroll
            for (int c = 0; c < 4; c++) acc[a][b][c] = 0.f;

    // prologue: chunks 0,1 into stages 0,1
    #pragma unroll
    for (int s = 0; s < 2; s++) {
        size_t srcA = a_src_base + s * 8;
        cpa16(aH + a_st + s * 4096, &Ah[srcA], a_valid);
        cpa16(aL + a_st + s * 4096, &Al[srcA], a_valid);
        if (do_b) {
            size_t srcB = b_src_base + s * 8;
            cpa16(bH + b_st + s * 2048, &Wh[srcB], 16);
            cpa16(bL + b_st + s * 2048, &Wl[srcB], 16);
        }
        CPA_COMMIT();
    }

    int st_cur = 0;   // ch % 3
    int st_wr  = 2;   // (ch+2) % 3
    for (int ch = 0; ch < 16; ch++) {          // 16 chunks of k16
        CPA_WAIT1();
        __syncthreads();
        if (ch + 2 < 16) {
            size_t srcA = a_src_base + (ch + 2) * 8;
            cpa16(aH + a_st + (uint32_t)st_wr * 4096, &Ah[srcA], a_valid);
            cpa16(aL + a_st + (uint32_t)st_wr * 4096, &Al[srcA], a_valid);
            if (do_b) {
                size_t srcB = b_src_base + (ch + 2) * 8;
                cpa16(bH + b_st + (uint32_t)st_wr * 2048, &Wh[srcB], 16);
                cpa16(bL + b_st + (uint32_t)st_wr * 2048, &Wl[srcB], 16);
            }
        }
        CPA_COMMIT();

        uint32_t soA = (uint32_t)st_cur * 4096;
        uint32_t soB = (uint32_t)st_cur * 2048;

        unsigned ah[2][4], al[2][4];
        #pragma unroll
        for (int mt = 0; mt < 2; mt++) {
            ldsm_x4(ah[mt], aH + soA + a_frag + mt * 256);
            ldsm_x4(al[mt], aL + soA + a_frag + mt * 256);
        }
        #pragma unroll
        for (int nt2 = 0; nt2 < 2; nt2++) {
            unsigned bh4[4], bl4[4];
            ldsm_x4(bh4, bH + soB + b_frag + nt2 * 256);
            ldsm_x4(bl4, bL + soB + b_frag + nt2 * 256);
            float* c0 = acc[0][2 * nt2];
            float* c1 = acc[0][2 * nt2 + 1];
            float* d0 = acc[1][2 * nt2];
            float* d1 = acc[1][2 * nt2 + 1];
            mma16(c0, ah[0], bl4[0], bl4[1]);
            mma16(d0, ah[1], bl4[0], bl4[1]);
            mma16(c1, ah[0], bl4[2], bl4[3]);
            mma16(d1, ah[1], bl4[2], bl4[3]);
            mma16(c0, al[0], bh4[0], bh4[1]);
            mma16(d0, al[1], bh4[0], bh4[1]);
            mma16(c1, al[0], bh4[2], bh4[3]);
            mma16(d1, al[1], bh4[2], bh4[3]);
            mma16(c0, ah[0], bh4[0], bh4[1]);
            mma16(d0, ah[1], bh4[0], bh4[1]);
            mma16(c1, ah[0], bh4[2], bh4[3]);
            mma16(d1, ah[1], bh4[2], bh4[3]);
        }
        st_cur++; if (st_cur == 3) st_cur = 0;
        st_wr++;  if (st_wr == 3)  st_wr = 0;
    }
    __syncthreads();

    #pragma unroll
    for (int mt = 0; mt < 2; mt++) {
        int rr = bm + warp_m * 32 + mt * 16 + gid;
        float a_r0 = 0.f, a_r8 = 0.f;
        if (MODE == 2) {
            if (rr < M)     a_r0 = g_a[rr];
            if (rr + 8 < M) a_r8 = g_a[rr + 8];
        }
        #pragma unroll
        for (int nt = 0; nt < 4; nt++) {
            int c = bn + warp_n * 32 + nt * 8 + tig * 2;
            float v0 = acc[mt][nt][0], v1 = acc[mt][nt][1];
            float v2 = acc[mt][nt][2], v3 = acc[mt][nt][3];
            if (MODE == 0) {
                float bb0 = bias[c], bb1 = bias[c + 1];
                v0 = fmaxf(v0 + bb0, 0.f); v1 = fmaxf(v1 + bb1, 0.f);
                v2 = fmaxf(v2 + bb0, 0.f); v3 = fmaxf(v3 + bb1, 0.f);
                if (rr < M)     *(float2*)&g_t[(size_t)rr * 256 + c]       = make_float2(v0, v1);
                if (rr + 8 < M) *(float2*)&g_t[(size_t)(rr + 8) * 256 + c] = make_float2(v2, v3);
            } else {
                float bv0 = g_bvec[c], bv1 = g_bvec[c + 1];
                float bc0 = g_bc2[c],  bc1 = g_bc2[c + 1];
                v0 += a_r0 * bv0 + bc0; v1 += a_r0 * bv1 + bc1;
                v2 += a_r8 * bv0 + bc0; v3 += a_r8 * bv1 + bc1;
                float* base = (c < 128) ? Cout : (Cout + (size_t)NN * 128);
                int cc = (c < 128) ? c : c - 128;
                if (rr < M)     *(float2*)&base[(size_t)rr * 128 + cc]       = make_float2(v0, v1);
                if (rr + 8 < M) *(float2*)&base[(size_t)(rr + 8) * 128 + cc] = make_float2(v2, v3);
            }
        }
    }
}

// ---------------- SpMM: column-half passes for L2 residency ----------------
// PHASE 0: g_t -> g_h1 (f32).  PHASE 1: g_h1 -> split s into P.
// HALF selects feature columns [HALF*128, HALF*128+128).
template<int PHASE, int HALF>
__global__ __launch_bounds__(256)
void spmm_kernel(int n) {
    const float* feat = (PHASE == 0) ? g_t : g_h1;
    int warp = (blockIdx.x * blockDim.x + threadIdx.x) >> 5;
    int lane = threadIdx.x & 31;
    if (warp >= n) return;
    int beg = g_rowptr[warp];
    int end = g_rowptr[warp + 1];
    const float4* f4 = (const float4*)feat;
    const int co = HALF * 32;   // float4 offset within row (64 per row)
    float4 acc0 = make_float4(0.f, 0.f, 0.f, 0.f);
    int e = beg;
    for (; e + 1 < end; e += 2) {
        int   r0 = g_src[e],     r1 = g_src[e + 1];
        float w0 = g_val[e],     w1 = g_val[e + 1];
        float4 a0 = f4[(size_t)r0 * 64 + co + lane];
        float4 a1 = f4[(size_t)r1 * 64 + co + lane];
        acc0.x = fmaf(w0, a0.x, acc0.x); acc0.y = fmaf(w0, a0.y, acc0.y);
        acc0.z = fmaf(w0, a0.z, acc0.z); acc0.w = fmaf(w0, a0.w, acc0.w);
        acc0.x = fmaf(w1, a1.x, acc0.x); acc0.y = fmaf(w1, a1.y, acc0.y);
        acc0.z = fmaf(w1, a1.z, acc0.z); acc0.w = fmaf(w1, a1.w, acc0.w);
    }
    if (e < end) {
        int   r = g_src[e];
        float v = g_val[e];
        float4 a = f4[(size_t)r * 64 + co + lane];
        acc0.x = fmaf(v, a.x, acc0.x); acc0.y = fmaf(v, a.y, acc0.y);
        acc0.z = fmaf(v, a.z, acc0.z); acc0.w = fmaf(v, a.w, acc0.w);
    }
    float di = g_dinv[warp];
    float d2 = di * di;
    float4 s0 = f4[(size_t)warp * 64 + co + lane];
    float4 o0;
    o0.x = di * acc0.x + d2 * s0.x; o0.y = di * acc0.y + d2 * s0.y;
    o0.z = di * acc0.z + d2 * s0.z; o0.w = di * acc0.w + d2 * s0.w;
    if (PHASE == 0) {
        ((float4*)g_h1)[(size_t)warp * 64 + co + lane] = o0;
    } else {
        unsigned h, l;
        size_t base = (size_t)warp * 128 + HALF * 64;
        split_pair(o0.x, o0.y, h, l);
        g_ph[base + 2 * lane] = h;     g_pl[base + 2 * lane] = l;
        split_pair(o0.z, o0.w, h, l);
        g_ph[base + 2 * lane + 1] = h; g_pl[base + 2 * lane + 1] = l;
    }
}

// ---------------- launch ----------------
extern "C" void kernel_launch(void* const* d_in, const int* in_sizes, int n_in,
                              void* d_out, int out_size) {
    const float* x  = (const float*)d_in[0];
    const void*  ei = d_in[1];
    const float* ew = (const float*)d_in[2];
    const float* wd = (const float*)d_in[3];
    const float* bd = (const float*)d_in[4];
    const float* we = (const float*)d_in[5];
    const float* be = (const float*)d_in[6];
    const float* wm = (const float*)d_in[7];
    const float* bmu = (const float*)d_in[8];
    const float* wl = (const float*)d_in[9];
    const float* bl = (const float*)d_in[10];
    float* out = (float*)d_out;

    const int n = NN;
    const int e = EE;

    dim3 grid(4, (n + 127) / 128);   // 128x64 tiles over 256 cols
    int spmm_blocks = (n * 32 + 255) / 256;

    // first GEMM pinned at launch index 3 for the ncu capture slot
    detect_kernel<<<1, 1024>>>((const int*)ei, 2 * e);                    // 0
    split_x_kernel<<<(NN * 64 + 255) / 256, 256>>>(x);                    // 1
    split_wd_kernel<<<128, 256>>>(wd);                                    // 2
    gemm_tc<0><<<grid, 256>>>(bd, nullptr, n);                            // 3: h0 -> g_t
    w2_kernel<<<256, 256>>>(we, wm, wl);                                  // 4
    bvec_kernel<<<1, 256>>>(be, wm, wl, bmu, bl);                         // 5
    init_kernel<<<(n + 255) / 256, 256>>>(n);                             // 6
    edge_pass<<<(e + 255) / 256, 256>>>(ei, ew, e);                       // 7
    dinv_kernel<<<(n + 255) / 256, 256>>>(n);                             // 8
    scan_kernel<<<1, 1024>>>(n);                                          // 9
    scatter_kernel<<<(e + 255) / 256, 256>>>(ei, ew, e);                  // 10
    rowsum_kernel<<<(n + 255) / 256, 256>>>(n);                           // 11
    split_w2_kernel<<<128, 256>>>();                                      // 12
    spmm_kernel<0, 0><<<spmm_blocks, 256>>>(n);                           // 13
    spmm_kernel<0, 1><<<spmm_blocks, 256>>>(n);                           // 14
    spmm_kernel<1, 0><<<spmm_blocks, 256>>>(n);                           // 15
    spmm_kernel<1, 1><<<spmm_blocks, 256>>>(n);                           // 16
    gemm_tc<2><<<grid, 256>>>(nullptr, out, n);                           // 17: out
}

// round 15
// speedup vs baseline: 1.3503x; 1.0562x over previous
#include <cuda_runtime.h>
#include <cstdint>

#define NN   100000
#define EE   1600000
#define KDIM 256

// ---------------- scratch (device globals) ----------------
__device__ unsigned g_ph[(size_t)NN * 128];  // split A operand (x, later s) [row][kpair]
__device__ unsigned g_pl[(size_t)NN * 128];
__device__ float    g_t [(size_t)NN * KDIM]; // h0 (f32)
__device__ float    g_h1[(size_t)NN * KDIM]; // u = A@h0 (f32)
__device__ unsigned g_wdh[256 * 128], g_wdl[256 * 128];
__device__ unsigned g_w2h[256 * 128], g_w2l[256 * 128];
__device__ float    g_w2f[256 * 256];        // We @ Wcat
__device__ float    g_bvec[256];             // be^T @ Wcat
__device__ float    g_bc2[256];              // [bmu | bl]
__device__ float    g_a[NN];                 // rowsum of A_norm
__device__ float g_deg[NN];
__device__ float g_dinv[NN];
__device__ int   g_cnt[NN];
__device__ int   g_rowptr[NN + 1];
__device__ int   g_cursor[NN];
__device__ int   g_src[EE];
__device__ float g_val[EE];
__device__ int   g_is64;

// ---------------- helpers ----------------
__device__ __forceinline__ void split_pair(float x0, float x1,
                                           unsigned& hi, unsigned& lo) {
    unsigned h;
    asm("cvt.rn.bf16x2.f32 %0, %1, %2;" : "=r"(h) : "f"(x1), "f"(x0));
    float h0 = __uint_as_float(h << 16);
    float h1 = __uint_as_float(h & 0xffff0000u);
    float r0 = x0 - h0, r1 = x1 - h1;
    unsigned l;
    asm("cvt.rn.bf16x2.f32 %0, %1, %2;" : "=r"(l) : "f"(r1), "f"(r0));
    hi = h; lo = l;
}

__device__ __forceinline__ uint32_t smem_u32(const void* p) {
    uint32_t a;
    asm("{ .reg .u64 t; cvta.to.shared.u64 t, %1; cvt.u32.u64 %0, t; }"
        : "=r"(a) : "l"(p));
    return a;
}

__device__ __forceinline__ void ldsm_x4(unsigned r[4], uint32_t addr) {
    asm volatile("ldmatrix.sync.aligned.m8n8.x4.shared.b16 {%0,%1,%2,%3}, [%4];"
        : "=r"(r[0]), "=r"(r[1]), "=r"(r[2]), "=r"(r[3]) : "r"(addr));
}

__device__ __forceinline__ void mma16(float c[4], const unsigned a[4],
                                      unsigned b0, unsigned b1) {
    asm volatile(
        "mma.sync.aligned.m16n8k16.row.col.f32.bf16.bf16.f32 "
        "{%0,%1,%2,%3}, {%4,%5,%6,%7}, {%8,%9}, {%0,%1,%2,%3};"
        : "+f"(c[0]), "+f"(c[1]), "+f"(c[2]), "+f"(c[3])
        : "r"(a[0]), "r"(a[1]), "r"(a[2]), "r"(a[3]), "r"(b0), "r"(b1));
}

__device__ __forceinline__ void cpa16(uint32_t dst, const void* src, int sz) {
    asm volatile("cp.async.cg.shared.global [%0], [%1], 16, %2;"
                 :: "r"(dst), "l"(src), "r"(sz) : "memory");
}
#define CPA_COMMIT() asm volatile("cp.async.commit_group;" ::: "memory")
#define CPA_WAIT1()  asm volatile("cp.async.wait_group 1;" ::: "memory")

// ---------------- edge-index dtype detection ----------------
__global__ void detect_kernel(const int* __restrict__ ei32, int n_int32) {
    __shared__ int any;
    if (threadIdx.x == 0) any = 0;
    __syncthreads();
    for (int i = threadIdx.x; i < 4096; i += blockDim.x) {
        int pos = 2 * i + 1;
        if (pos < n_int32 && ei32[pos] != 0) any = 1;
    }
    __syncthreads();
    if (threadIdx.x == 0) g_is64 = (any == 0) ? 1 : 0;
}

__device__ __forceinline__ int load_idx(const void* ei, int e, int part, int i) {
    if (g_is64) return (int)((const long long*)ei)[(size_t)part * e + i];
    return ((const int*)ei)[(size_t)part * e + i];
}

// ---------------- graph preprocessing ----------------
__global__ void init_kernel(int n) {
    int i = blockIdx.x * blockDim.x + threadIdx.x;
    if (i < n) { g_deg[i] = 1.0f; g_cnt[i] = 0; }
}

__global__ void edge_pass(const void* __restrict__ ei,
                          const float* __restrict__ ew, int e) {
    int i = blockIdx.x * blockDim.x + threadIdx.x;
    if (i >= e) return;
    int c = load_idx(ei, e, 1, i);
    if ((unsigned)c >= NN) return;
    atomicAdd(&g_deg[c], ew[i]);
    atomicAdd(&g_cnt[c], 1);
}

__global__ void dinv_kernel(int n) {
    int i = blockIdx.x * blockDim.x + threadIdx.x;
    if (i < n) g_dinv[i] = rsqrtf(g_deg[i]);
}

__global__ void scan_kernel(int n) {
    __shared__ int part[1024];
    int tid = threadIdx.x;
    int chunk = (n + 1023) >> 10;
    int beg = tid * chunk;
    int end = beg + chunk; if (end > n) end = n;
    int s = 0;
    for (int i = beg; i < end; i++) s += g_cnt[i];
    part[tid] = s;
    __syncthreads();
    for (int off = 1; off < 1024; off <<= 1) {
        int v = (tid >= off) ? part[tid - off] : 0;
        __syncthreads();
        part[tid] += v;
        __syncthreads();
    }
    int run = (tid > 0) ? part[tid - 1] : 0;
    for (int i = beg; i < end; i++) {
        g_rowptr[i] = run; g_cursor[i] = run; run += g_cnt[i];
    }
    if (tid == 1023) g_rowptr[n] = part[1023];
}

__global__ void scatter_kernel(const void* __restrict__ ei,
                               const float* __restrict__ ew, int e) {
    int i = blockIdx.x * blockDim.x + threadIdx.x;
    if (i >= e) return;
    int r = load_idx(ei, e, 0, i);
    int c = load_idx(ei, e, 1, i);
    if ((unsigned)r >= NN || (unsigned)c >= NN) return;
    int pos = atomicAdd(&g_cursor[c], 1);
    g_src[pos] = r;
    g_val[pos] = ew[i] * g_dinv[r];
}

// a = A_norm @ 1
__global__ void rowsum_kernel(int n) {
    int i = blockIdx.x * blockDim.x + threadIdx.x;
    if (i >= n) return;
    float s = 0.f;
    int beg = g_rowptr[i], end = g_rowptr[i + 1];
    for (int e = beg; e < end; e++) s += g_val[e];
    float di = g_dinv[i];
    g_a[i] = di * s + di * di;
}

// ---------------- composed-weight kernels ----------------
__global__ void w2_kernel(const float* __restrict__ we,
                          const float* __restrict__ wm,
                          const float* __restrict__ wl) {
    int idx = blockIdx.x * blockDim.x + threadIdx.x;
    if (idx >= 256 * 256) return;
    int k = idx >> 8, n = idx & 255;
    float s = 0.f;
    if (n < 128) {
        for (int j = 0; j < 256; j++) s = fmaf(we[k * 256 + j], wm[j * 128 + n], s);
    } else {
        int nn = n - 128;
        for (int j = 0; j < 256; j++) s = fmaf(we[k * 256 + j], wl[j * 128 + nn], s);
    }
    g_w2f[idx] = s;
}

__global__ void bvec_kernel(const float* __restrict__ be,
                            const float* __restrict__ wm,
                            const float* __restrict__ wl,
                            const float* __restrict__ bmu,
                            const float* __restrict__ bl) {
    int n = blockIdx.x * blockDim.x + threadIdx.x;
    if (n >= 256) return;
    float s = 0.f;
    if (n < 128) {
        for (int k = 0; k < 256; k++) s = fmaf(be[k], wm[k * 128 + n], s);
        g_bc2[n] = bmu[n];
    } else {
        int nn = n - 128;
        for (int k = 0; k < 256; k++) s = fmaf(be[k], wl[k * 128 + nn], s);
        g_bc2[n] = bl[nn];
    }
    g_bvec[n] = s;
}

// ---------------- split kernels ----------------
__global__ void split_x_kernel(const float* __restrict__ src) {
    int i = blockIdx.x * blockDim.x + threadIdx.x;
    if (i >= NN * 64) return;
    float4 v = ((const float4*)src)[i];
    unsigned h0, l0, h1, l1;
    split_pair(v.x, v.y, h0, l0);
    split_pair(v.z, v.w, h1, l1);
    ((uint2*)g_ph)[i] = make_uint2(h0, h1);
    ((uint2*)g_pl)[i] = make_uint2(l0, l1);
}

__global__ void split_wd_kernel(const float* __restrict__ w0) {
    int i = blockIdx.x * blockDim.x + threadIdx.x;
    if (i >= 256 * 128) return;
    int n = i >> 7, j = i & 127;
    unsigned h, l;
    split_pair(w0[(2 * j) * 256 + n], w0[(2 * j + 1) * 256 + n], h, l);
    g_wdh[i] = h; g_wdl[i] = l;
}

__global__ void split_w2_kernel() {
    int i = blockIdx.x * blockDim.x + threadIdx.x;
    if (i >= 256 * 128) return;
    int n = i >> 7, j = i & 127;
    unsigned h, l;
    split_pair(g_w2f[(2 * j) * 256 + n], g_w2f[(2 * j + 1) * 256 + n], h, l);
    g_w2h[i] = h; g_w2l[i] = l;
}

// ---------------- 3-stage pipelined TC GEMM, 128x128 tile (R13 config) -------------
// MODE 0: A=P(x), W=wd split, +bias +relu, f32 -> g_t
// MODE 2: A=P(s), W=w2 split, epilogue v += a[r]*bvec[c] + bc2[c], split halves -> Cout
template<int MODE>
__global__ __launch_bounds__(256, 2)
void gemm_tc(const float* __restrict__ bias, float* __restrict__ Cout, int M) {
    const unsigned* Ah = g_ph;
    const unsigned* Al = g_pl;
    const unsigned* Wh = (MODE == 0) ? g_wdh : g_w2h;
    const unsigned* Wl = (MODE == 0) ? g_wdl : g_w2l;

    __shared__ unsigned sAh[3 * 2 * 128 * 4];   // 12KB each
    __shared__ unsigned sAl[3 * 2 * 128 * 4];
    __shared__ unsigned sBh[3 * 2 * 128 * 4];
    __shared__ unsigned sBl[3 * 2 * 128 * 4];

    int tid  = threadIdx.x;
    int lane = tid & 31, wid = tid >> 5;
    int warp_m = wid & 3, warp_n = wid >> 2;
    int bm = blockIdx.y * 128;
    int bn = blockIdx.x * 128;
    int gid = lane >> 2, tig = lane & 3;

    uint32_t aH = smem_u32(sAh), aL = smem_u32(sAl);
    uint32_t bH = smem_u32(sBh), bL = smem_u32(sBl);

    int ld_row = tid & 127;
    int ld_plane = tid >> 7;
    int a_valid = (bm + ld_row < M) ? 16 : 0;
    uint32_t st_off = (uint32_t)(ld_plane * 2048 + ld_row * 16);
    size_t a_src_base = (size_t)(bm + ld_row) * 128 + ld_plane * 4;
    size_t b_src_base = (size_t)(bn + ld_row) * 128 + ld_plane * 4;

    int lr = lane & 7;
    uint32_t a_frag = (uint32_t)((lane >> 4) * 2048
                    + (warp_m * 32 + lr + ((lane >> 3) & 1) * 8) * 16);
    uint32_t b_frag = (uint32_t)(((lane >> 3) & 1) * 2048
                    + (warp_n * 64 + lr + ((lane >> 4) ? 8 : 0)) * 16);

    float acc[2][8][4];
    #pragma unroll
    for (int a = 0; a < 2; a++)
        #pragma unroll
        for (int b = 0; b < 8; b++)
            #pragma unroll
            for (int c = 0; c < 4; c++) acc[a][b][c] = 0.f;

    #pragma unroll
    for (int s = 0; s < 2; s++) {
        uint32_t dst = st_off + s * 4096;
        size_t srcA = a_src_base + s * 8;
        size_t srcB = b_src_base + s * 8;
        cpa16(aH + dst, &Ah[srcA], a_valid);
        cpa16(aL + dst, &Al[srcA], a_valid);
        cpa16(bH + dst, &Wh[srcB], 16);
        cpa16(bL + dst, &Wl[srcB], 16);
        CPA_COMMIT();
    }

    int st_cur = 0;
    int st_wr  = 2;
    for (int ch = 0; ch < 16; ch++) {
        CPA_WAIT1();
        __syncthreads();
        if (ch + 2 < 16) {
            uint32_t dst = st_off + (uint32_t)st_wr * 4096;
            size_t srcA = a_src_base + (ch + 2) * 8;
            size_t srcB = b_src_base + (ch + 2) * 8;
            cpa16(aH + dst, &Ah[srcA], a_valid);
            cpa16(aL + dst, &Al[srcA], a_valid);
            cpa16(bH + dst, &Wh[srcB], 16);
            cpa16(bL + dst, &Wl[srcB], 16);
        }
        CPA_COMMIT();

        uint32_t so = (uint32_t)st_cur * 4096;

        unsigned ah[2][4], al[2][4];
        #pragma unroll
        for (int mt = 0; mt < 2; mt++) {
            ldsm_x4(ah[mt], aH + so + a_frag + mt * 256);
            ldsm_x4(al[mt], aL + so + a_frag + mt * 256);
        }
        #pragma unroll
        for (int nt2 = 0; nt2 < 4; nt2++) {
            unsigned bh4[4], bl4[4];
            ldsm_x4(bh4, bH + so + b_frag + nt2 * 256);
            ldsm_x4(bl4, bL + so + b_frag + nt2 * 256);
            float* c0 = acc[0][2 * nt2];
            float* c1 = acc[0][2 * nt2 + 1];
            float* d0 = acc[1][2 * nt2];
            float* d1 = acc[1][2 * nt2 + 1];
            mma16(c0, ah[0], bl4[0], bl4[1]);
            mma16(d0, ah[1], bl4[0], bl4[1]);
            mma16(c1, ah[0], bl4[2], bl4[3]);
            mma16(d1, ah[1], bl4[2], bl4[3]);
            mma16(c0, al[0], bh4[0], bh4[1]);
            mma16(d0, al[1], bh4[0], bh4[1]);
            mma16(c1, al[0], bh4[2], bh4[3]);
            mma16(d1, al[1], bh4[2], bh4[3]);
            mma16(c0, ah[0], bh4[0], bh4[1]);
            mma16(d0, ah[1], bh4[0], bh4[1]);
            mma16(c1, ah[0], bh4[2], bh4[3]);
            mma16(d1, ah[1], bh4[2], bh4[3]);
        }
        st_cur++; if (st_cur == 3) st_cur = 0;
        st_wr++;  if (st_wr == 3)  st_wr = 0;
    }
    __syncthreads();

    #pragma unroll
    for (int mt = 0; mt < 2; mt++) {
        int rr = bm + warp_m * 32 + mt * 16 + gid;
        float a_r0 = 0.f, a_r8 = 0.f;
        if (MODE == 2) {
            if (rr < M)     a_r0 = g_a[rr];
            if (rr + 8 < M) a_r8 = g_a[rr + 8];
        }
        #pragma unroll
        for (int nt = 0; nt < 8; nt++) {
            int c = bn + warp_n * 64 + nt * 8 + tig * 2;
            float v0 = acc[mt][nt][0], v1 = acc[mt][nt][1];
            float v2 = acc[mt][nt][2], v3 = acc[mt][nt][3];
            if (MODE == 0) {
                float bb0 = bias[c], bb1 = bias[c + 1];
                v0 = fmaxf(v0 + bb0, 0.f); v1 = fmaxf(v1 + bb1, 0.f);
                v2 = fmaxf(v2 + bb0, 0.f); v3 = fmaxf(v3 + bb1, 0.f);
                if (rr < M)     *(float2*)&g_t[(size_t)rr * 256 + c]       = make_float2(v0, v1);
                if (rr + 8 < M) *(float2*)&g_t[(size_t)(rr + 8) * 256 + c] = make_float2(v2, v3);
            } else {
                float bv0 = g_bvec[c], bv1 = g_bvec[c + 1];
                float bc0 = g_bc2[c],  bc1 = g_bc2[c + 1];
                v0 += a_r0 * bv0 + bc0; v1 += a_r0 * bv1 + bc1;
                v2 += a_r8 * bv0 + bc0; v3 += a_r8 * bv1 + bc1;
                float* base = (c < 128) ? Cout : (Cout + (size_t)NN * 128);
                int cc = (c < 128) ? c : c - 128;
                if (rr < M)     *(float2*)&base[(size_t)rr * 128 + cc]       = make_float2(v0, v1);
                if (rr + 8 < M) *(float2*)&base[(size_t)(rr + 8) * 128 + cc] = make_float2(v2, v3);
            }
        }
    }
}

// ---------------- SpMM: column-half passes for L2 residency ----------------
// PHASE 0: g_t -> g_h1 (f32).  PHASE 1: g_h1 -> split s into P.
template<int PHASE, int HALF>
__global__ __launch_bounds__(256)
void spmm_kernel(int n) {
    const float* feat = (PHASE == 0) ? g_t : g_h1;
    int warp = (blockIdx.x * blockDim.x + threadIdx.x) >> 5;
    int lane = threadIdx.x & 31;
    if (warp >= n) return;
    int beg = g_rowptr[warp];
    int end = g_rowptr[warp + 1];
    const float4* f4 = (const float4*)feat;
    const int co = HALF * 32;   // float4 offset within row (64 per row)
    float4 acc0 = make_float4(0.f, 0.f, 0.f, 0.f);
    int e = beg;
    for (; e + 1 < end; e += 2) {
        int   r0 = g_src[e],     r1 = g_src[e + 1];
        float w0 = g_val[e],     w1 = g_val[e + 1];
        float4 a0 = f4[(size_t)r0 * 64 + co + lane];
        float4 a1 = f4[(size_t)r1 * 64 + co + lane];
        acc0.x = fmaf(w0, a0.x, acc0.x); acc0.y = fmaf(w0, a0.y, acc0.y);
        acc0.z = fmaf(w0, a0.z, acc0.z); acc0.w = fmaf(w0, a0.w, acc0.w);
        acc0.x = fmaf(w1, a1.x, acc0.x); acc0.y = fmaf(w1, a1.y, acc0.y);
        acc0.z = fmaf(w1, a1.z, acc0.z); acc0.w = fmaf(w1, a1.w, acc0.w);
    }
    if (e < end) {
        int   r = g_src[e];
        float v = g_val[e];
        float4 a = f4[(size_t)r * 64 + co + lane];
        acc0.x = fmaf(v, a.x, acc0.x); acc0.y = fmaf(v, a.y, acc0.y);
        acc0.z = fmaf(v, a.z, acc0.z); acc0.w = fmaf(v, a.w, acc0.w);
    }
    float di = g_dinv[warp];
    float d2 = di * di;
    float4 s0 = f4[(size_t)warp * 64 + co + lane];
    float4 o0;
    o0.x = di * acc0.x + d2 * s0.x; o0.y = di * acc0.y + d2 * s0.y;
    o0.z = di * acc0.z + d2 * s0.z; o0.w = di * acc0.w + d2 * s0.w;
    if (PHASE == 0) {
        ((float4*)g_h1)[(size_t)warp * 64 + co + lane] = o0;
    } else {
        unsigned h, l;
        size_t base = (size_t)warp * 128 + HALF * 64;
        split_pair(o0.x, o0.y, h, l);
        g_ph[base + 2 * lane] = h;     g_pl[base + 2 * lane] = l;
        split_pair(o0.z, o0.w, h, l);
        g_ph[base + 2 * lane + 1] = h; g_pl[base + 2 * lane + 1] = l;
    }
}

// ---------------- launch ----------------
extern "C" void kernel_launch(void* const* d_in, const int* in_sizes, int n_in,
                              void* d_out, int out_size) {
    const float* x  = (const float*)d_in[0];
    const void*  ei = d_in[1];
    const float* ew = (const float*)d_in[2];
    const float* wd = (const float*)d_in[3];
    const float* bd = (const float*)d_in[4];
    const float* we = (const float*)d_in[5];
    const float* be = (const float*)d_in[6];
    const float* wm = (const float*)d_in[7];
    const float* bmu = (const float*)d_in[8];
    const float* wl = (const float*)d_in[9];
    const float* bl = (const float*)d_in[10];
    float* out = (float*)d_out;

    const int n = NN;
    const int e = EE;

    dim3 grid(2, (n + 127) / 128);   // 128x128 tiles over 256 cols
    int spmm_blocks = (n * 32 + 255) / 256;

    // first GEMM pinned at launch index 3 for the ncu capture slot
    detect_kernel<<<1, 1024>>>((const int*)ei, 2 * e);                    // 0
    split_x_kernel<<<(NN * 64 + 255) / 256, 256>>>(x);                    // 1
    split_wd_kernel<<<128, 256>>>(wd);                                    // 2
    gemm_tc<0><<<grid, 256>>>(bd, nullptr, n);                            // 3: h0 -> g_t
    w2_kernel<<<256, 256>>>(we, wm, wl);                                  // 4
    bvec_kernel<<<1, 256>>>(be, wm, wl, bmu, bl);                         // 5
    init_kernel<<<(n + 255) / 256, 256>>>(n);                             // 6
    edge_pass<<<(e + 255) / 256, 256>>>(ei, ew, e);                       // 7
    dinv_kernel<<<(n + 255) / 256, 256>>>(n);                             // 8
    scan_kernel<<<1, 1024>>>(n);                                          // 9
    scatter_kernel<<<(e + 255) / 256, 256>>>(ei, ew, e);                  // 10
    rowsum_kernel<<<(n + 255) / 256, 256>>>(n);                           // 11
    split_w2_kernel<<<128, 256>>>();                                      // 12
    spmm_kernel<0, 0><<<spmm_blocks, 256>>>(n);                           // 13
    spmm_kernel<0, 1><<<spmm_blocks, 256>>>(n);                           // 14
    spmm_kernel<1, 0><<<spmm_blocks, 256>>>(n);                           // 15
    spmm_kernel<1, 1><<<spmm_blocks, 256>>>(n);                           // 16
    gemm_tc<2><<<grid, 256>>>(nullptr, out, n);                           // 17: out
}

// round 16
// speedup vs baseline: 1.4161x; 1.0488x over previous
#include <cuda_runtime.h>
#include <cstdint>

#define NN   100000
#define EE   1600000
#define KDIM 256

// ---------------- scratch (device globals) ----------------
__device__ unsigned g_ph[(size_t)NN * 128];  // split A operand (x, later s) [row][kpair]
__device__ unsigned g_pl[(size_t)NN * 128];
__device__ float    g_t [(size_t)NN * KDIM]; // h0 (f32)
__device__ float    g_h1[(size_t)NN * KDIM]; // u = A@h0 (f32)
__device__ unsigned g_wdh[256 * 128], g_wdl[256 * 128];
__device__ unsigned g_w2h[256 * 128], g_w2l[256 * 128];
__device__ float    g_w2f[256 * 256];        // We @ Wcat
__device__ float    g_bvec[256];             // be^T @ Wcat
__device__ float    g_bc2[256];              // [bmu | bl]
__device__ float    g_a[NN];                 // rowsum of A_norm
__device__ float g_deg[NN];
__device__ float g_dinv[NN];
__device__ int   g_cnt[NN];
__device__ int   g_rowptr[NN + 1];
__device__ int   g_cursor[NN];
__device__ int   g_src[EE];
__device__ float g_val[EE];
__device__ int   g_is64;

// ---------------- helpers ----------------
__device__ __forceinline__ void split_pair(float x0, float x1,
                                           unsigned& hi, unsigned& lo) {
    unsigned h;
    asm("cvt.rn.bf16x2.f32 %0, %1, %2;" : "=r"(h) : "f"(x1), "f"(x0));
    float h0 = __uint_as_float(h << 16);
    float h1 = __uint_as_float(h & 0xffff0000u);
    float r0 = x0 - h0, r1 = x1 - h1;
    unsigned l;
    asm("cvt.rn.bf16x2.f32 %0, %1, %2;" : "=r"(l) : "f"(r1), "f"(r0));
    hi = h; lo = l;
}

__device__ __forceinline__ uint32_t smem_u32(const void* p) {
    uint32_t a;
    asm("{ .reg .u64 t; cvta.to.shared.u64 t, %1; cvt.u32.u64 %0, t; }"
        : "=r"(a) : "l"(p));
    return a;
}

__device__ __forceinline__ void ldsm_x4(unsigned r[4], uint32_t addr) {
    asm volatile("ldmatrix.sync.aligned.m8n8.x4.shared.b16 {%0,%1,%2,%3}, [%4];"
        : "=r"(r[0]), "=r"(r[1]), "=r"(r[2]), "=r"(r[3]) : "r"(addr));
}

__device__ __forceinline__ void mma16(float c[4], const unsigned a[4],
                                      unsigned b0, unsigned b1) {
    asm volatile(
        "mma.sync.aligned.m16n8k16.row.col.f32.bf16.bf16.f32 "
        "{%0,%1,%2,%3}, {%4,%5,%6,%7}, {%8,%9}, {%0,%1,%2,%3};"
        : "+f"(c[0]), "+f"(c[1]), "+f"(c[2]), "+f"(c[3])
        : "r"(a[0]), "r"(a[1]), "r"(a[2]), "r"(a[3]), "r"(b0), "r"(b1));
}

__device__ __forceinline__ void cpa16(uint32_t dst, const void* src, int sz) {
    asm volatile("cp.async.cg.shared.global [%0], [%1], 16, %2;"
                 :: "r"(dst), "l"(src), "r"(sz) : "memory");
}
#define CPA_COMMIT() asm volatile("cp.async.commit_group;" ::: "memory")
#define CPA_WAIT1()  asm volatile("cp.async.wait_group 1;" ::: "memory")

// ---------------- edge-index dtype detection ----------------
__global__ void detect_kernel(const int* __restrict__ ei32, int n_int32) {
    __shared__ int any;
    if (threadIdx.x == 0) any = 0;
    __syncthreads();
    for (int i = threadIdx.x; i < 4096; i += blockDim.x) {
        int pos = 2 * i + 1;
        if (pos < n_int32 && ei32[pos] != 0) any = 1;
    }
    __syncthreads();
    if (threadIdx.x == 0) g_is64 = (any == 0) ? 1 : 0;
}

__device__ __forceinline__ int load_idx(const void* ei, int e, int part, int i) {
    if (g_is64) return (int)((const long long*)ei)[(size_t)part * e + i];
    return ((const int*)ei)[(size_t)part * e + i];
}

// ---------------- graph preprocessing ----------------
__global__ void init_kernel(int n) {
    int i = blockIdx.x * blockDim.x + threadIdx.x;
    if (i < n) { g_deg[i] = 1.0f; g_cnt[i] = 0; }
}

__global__ void edge_pass(const void* __restrict__ ei,
                          const float* __restrict__ ew, int e) {
    int i = blockIdx.x * blockDim.x + threadIdx.x;
    if (i >= e) return;
    int c = load_idx(ei, e, 1, i);
    if ((unsigned)c >= NN) return;
    atomicAdd(&g_deg[c], ew[i]);
    atomicAdd(&g_cnt[c], 1);
}

__global__ void dinv_kernel(int n) {
    int i = blockIdx.x * blockDim.x + threadIdx.x;
    if (i < n) g_dinv[i] = rsqrtf(g_deg[i]);
}

__global__ void scan_kernel(int n) {
    __shared__ int part[1024];
    int tid = threadIdx.x;
    int chunk = (n + 1023) >> 10;
    int beg = tid * chunk;
    int end = beg + chunk; if (end > n) end = n;
    int s = 0;
    for (int i = beg; i < end; i++) s += g_cnt[i];
    part[tid] = s;
    __syncthreads();
    for (int off = 1; off < 1024; off <<= 1) {
        int v = (tid >= off) ? part[tid - off] : 0;
        __syncthreads();
        part[tid] += v;
        __syncthreads();
    }
    int run = (tid > 0) ? part[tid - 1] : 0;
    for (int i = beg; i < end; i++) {
        g_rowptr[i] = run; g_cursor[i] = run; run += g_cnt[i];
    }
    if (tid == 1023) g_rowptr[n] = part[1023];
}

__global__ void scatter_kernel(const void* __restrict__ ei,
                               const float* __restrict__ ew, int e) {
    int i = blockIdx.x * blockDim.x + threadIdx.x;
    if (i >= e) return;
    int r = load_idx(ei, e, 0, i);
    int c = load_idx(ei, e, 1, i);
    if ((unsigned)r >= NN || (unsigned)c >= NN) return;
    int pos = atomicAdd(&g_cursor[c], 1);
    g_src[pos] = r;
    g_val[pos] = ew[i] * g_dinv[r];
}

// a = A_norm @ 1
__global__ void rowsum_kernel(int n) {
    int i = blockIdx.x * blockDim.x + threadIdx.x;
    if (i >= n) return;
    float s = 0.f;
    int beg = g_rowptr[i], end = g_rowptr[i + 1];
    for (int e = beg; e < end; e++) s += g_val[e];
    float di = g_dinv[i];
    g_a[i] = di * s + di * di;
}

// ---------------- composed-weight kernels ----------------
__global__ void w2_kernel(const float* __restrict__ we,
                          const float* __restrict__ wm,
                          const float* __restrict__ wl) {
    int idx = blockIdx.x * blockDim.x + threadIdx.x;
    if (idx >= 256 * 256) return;
    int k = idx >> 8, n = idx & 255;
    float s = 0.f;
    if (n < 128) {
        for (int j = 0; j < 256; j++) s = fmaf(we[k * 256 + j], wm[j * 128 + n], s);
    } else {
        int nn = n - 128;
        for (int j = 0; j < 256; j++) s = fmaf(we[k * 256 + j], wl[j * 128 + nn], s);
    }
    g_w2f[idx] = s;
}

__global__ void bvec_kernel(const float* __restrict__ be,
                            const float* __restrict__ wm,
                            const float* __restrict__ wl,
                            const float* __restrict__ bmu,
                            const float* __restrict__ bl) {
    int n = blockIdx.x * blockDim.x + threadIdx.x;
    if (n >= 256) return;
    float s = 0.f;
    if (n < 128) {
        for (int k = 0; k < 256; k++) s = fmaf(be[k], wm[k * 128 + n], s);
        g_bc2[n] = bmu[n];
    } else {
        int nn = n - 128;
        for (int k = 0; k < 256; k++) s = fmaf(be[k], wl[k * 128 + nn], s);
        g_bc2[n] = bl[nn];
    }
    g_bvec[n] = s;
}

// ---------------- split kernels ----------------
__global__ void split_x_kernel(const float* __restrict__ src) {
    int i = blockIdx.x * blockDim.x + threadIdx.x;
    if (i >= NN * 64) return;
    float4 v = ((const float4*)src)[i];
    unsigned h0, l0, h1, l1;
    split_pair(v.x, v.y, h0, l0);
    split_pair(v.z, v.w, h1, l1);
    ((uint2*)g_ph)[i] = make_uint2(h0, h1);
    ((uint2*)g_pl)[i] = make_uint2(l0, l1);
}

__global__ void split_wd_kernel(const float* __restrict__ w0) {
    int i = blockIdx.x * blockDim.x + threadIdx.x;
    if (i >= 256 * 128) return;
    int n = i >> 7, j = i & 127;
    unsigned h, l;
    split_pair(w0[(2 * j) * 256 + n], w0[(2 * j + 1) * 256 + n], h, l);
    g_wdh[i] = h; g_wdl[i] = l;
}

__global__ void split_w2_kernel() {
    int i = blockIdx.x * blockDim.x + threadIdx.x;
    if (i >= 256 * 128) return;
    int n = i >> 7, j = i & 127;
    unsigned h, l;
    split_pair(g_w2f[(2 * j) * 256 + n], g_w2f[(2 * j + 1) * 256 + n], h, l);
    g_w2h[i] = h; g_w2l[i] = l;
}

// ---------------- 3-stage pipelined TC GEMM, 128x128 tile -------------
// MODE 0: A=P(x), W=wd split, +bias +relu, f32 -> g_t
// MODE 2: A=P(s), W=w2 split, epilogue v += a[r]*bvec[c] + bc2[c], split halves -> Cout
template<int MODE>
__global__ __launch_bounds__(256, 2)
void gemm_tc(const float* __restrict__ bias, float* __restrict__ Cout, int M) {
    const unsigned* Ah = g_ph;
    const unsigned* Al = g_pl;
    const unsigned* Wh = (MODE == 0) ? g_wdh : g_w2h;
    const unsigned* Wl = (MODE == 0) ? g_wdl : g_w2l;

    __shared__ unsigned sAh[3 * 2 * 128 * 4];   // 12KB each
    __shared__ unsigned sAl[3 * 2 * 128 * 4];
    __shared__ unsigned sBh[3 * 2 * 128 * 4];
    __shared__ unsigned sBl[3 * 2 * 128 * 4];

    int tid  = threadIdx.x;
    int lane = tid & 31, wid = tid >> 5;
    int warp_m = wid & 3, warp_n = wid >> 2;
    int bm = blockIdx.y * 128;
    int bn = blockIdx.x * 128;
    int gid = lane >> 2, tig = lane & 3;

    uint32_t aH = smem_u32(sAh), aL = smem_u32(sAl);
    uint32_t bH = smem_u32(sBh), bL = smem_u32(sBl);

    int ld_row = tid & 127;
    int ld_plane = tid >> 7;
    int a_valid = (bm + ld_row < M) ? 16 : 0;
    uint32_t st_off = (uint32_t)(ld_plane * 2048 + ld_row * 16);
    size_t a_src_base = (size_t)(bm + ld_row) * 128 + ld_plane * 4;
    size_t b_src_base = (size_t)(bn + ld_row) * 128 + ld_plane * 4;

    int lr = lane & 7;
    uint32_t a_frag = (uint32_t)((lane >> 4) * 2048
                    + (warp_m * 32 + lr + ((lane >> 3) & 1) * 8) * 16);
    uint32_t b_frag = (uint32_t)(((lane >> 3) & 1) * 2048
                    + (warp_n * 64 + lr + ((lane >> 4) ? 8 : 0)) * 16);

    float acc[2][8][4];
    #pragma unroll
    for (int a = 0; a < 2; a++)
        #pragma unroll
        for (int b = 0; b < 8; b++)
            #pragma unroll
            for (int c = 0; c < 4; c++) acc[a][b][c] = 0.f;

    #pragma unroll
    for (int s = 0; s < 2; s++) {
        uint32_t dst = st_off + s * 4096;
        size_t srcA = a_src_base + s * 8;
        size_t srcB = b_src_base + s * 8;
        cpa16(aH + dst, &Ah[srcA], a_valid);
        cpa16(aL + dst, &Al[srcA], a_valid);
        cpa16(bH + dst, &Wh[srcB], 16);
        cpa16(bL + dst, &Wl[srcB], 16);
        CPA_COMMIT();
    }

    int st_cur = 0;
    int st_wr  = 2;
    for (int ch = 0; ch < 16; ch++) {
        CPA_WAIT1();
        __syncthreads();
        if (ch + 2 < 16) {
            uint32_t dst = st_off + (uint32_t)st_wr * 4096;
            size_t srcA = a_src_base + (ch + 2) * 8;
            size_t srcB = b_src_base + (ch + 2) * 8;
            cpa16(aH + dst, &Ah[srcA], a_valid);
            cpa16(aL + dst, &Al[srcA], a_valid);
            cpa16(bH + dst, &Wh[srcB], 16);
            cpa16(bL + dst, &Wl[srcB], 16);
        }
        CPA_COMMIT();

        uint32_t so = (uint32_t)st_cur * 4096;

        unsigned ah[2][4], al[2][4];
        #pragma unroll
        for (int mt = 0; mt < 2; mt++) {
            ldsm_x4(ah[mt], aH + so + a_frag + mt * 256);
            ldsm_x4(al[mt], aL + so + a_frag + mt * 256);
        }
        #pragma unroll
        for (int nt2 = 0; nt2 < 4; nt2++) {
            unsigned bh4[4], bl4[4];
            ldsm_x4(bh4, bH + so + b_frag + nt2 * 256);
            ldsm_x4(bl4, bL + so + b_frag + nt2 * 256);
            float* c0 = acc[0][2 * nt2];
            float* c1 = acc[0][2 * nt2 + 1];
            float* d0 = acc[1][2 * nt2];
            float* d1 = acc[1][2 * nt2 + 1];
            mma16(c0, ah[0], bl4[0], bl4[1]);
            mma16(d0, ah[1], bl4[0], bl4[1]);
            mma16(c1, ah[0], bl4[2], bl4[3]);
            mma16(d1, ah[1], bl4[2], bl4[3]);
            mma16(c0, al[0], bh4[0], bh4[1]);
            mma16(d0, al[1], bh4[0], bh4[1]);
            mma16(c1, al[0], bh4[2], bh4[3]);
            mma16(d1, al[1], bh4[2], bh4[3]);
            mma16(c0, ah[0], bh4[0], bh4[1]);
            mma16(d0, ah[1], bh4[0], bh4[1]);
            mma16(c1, ah[0], bh4[2], bh4[3]);
            mma16(d1, ah[1], bh4[2], bh4[3]);
        }
        st_cur++; if (st_cur == 3) st_cur = 0;
        st_wr++;  if (st_wr == 3)  st_wr = 0;
    }
    __syncthreads();

    #pragma unroll
    for (int mt = 0; mt < 2; mt++) {
        int rr = bm + warp_m * 32 + mt * 16 + gid;
        float a_r0 = 0.f, a_r8 = 0.f;
        if (MODE == 2) {
            if (rr < M)     a_r0 = g_a[rr];
            if (rr + 8 < M) a_r8 = g_a[rr + 8];
        }
        #pragma unroll
        for (int nt = 0; nt < 8; nt++) {
            int c = bn + warp_n * 64 + nt * 8 + tig * 2;
            float v0 = acc[mt][nt][0], v1 = acc[mt][nt][1];
            float v2 = acc[mt][nt][2], v3 = acc[mt][nt][3];
            if (MODE == 0) {
                float bb0 = bias[c], bb1 = bias[c + 1];
                v0 = fmaxf(v0 + bb0, 0.f); v1 = fmaxf(v1 + bb1, 0.f);
                v2 = fmaxf(v2 + bb0, 0.f); v3 = fmaxf(v3 + bb1, 0.f);
                if (rr < M)     *(float2*)&g_t[(size_t)rr * 256 + c]       = make_float2(v0, v1);
                if (rr + 8 < M) *(float2*)&g_t[(size_t)(rr + 8) * 256 + c] = make_float2(v2, v3);
            } else {
                float bv0 = g_bvec[c], bv1 = g_bvec[c + 1];
                float bc0 = g_bc2[c],  bc1 = g_bc2[c + 1];
                v0 += a_r0 * bv0 + bc0; v1 += a_r0 * bv1 + bc1;
                v2 += a_r8 * bv0 + bc0; v3 += a_r8 * bv1 + bc1;
                float* base = (c < 128) ? Cout : (Cout + (size_t)NN * 128);
                int cc = (c < 128) ? c : c - 128;
                if (rr < M)     *(float2*)&base[(size_t)rr * 128 + cc]       = make_float2(v0, v1);
                if (rr + 8 < M) *(float2*)&base[(size_t)(rr + 8) * 128 + cc] = make_float2(v2, v3);
            }
        }
    }
}

// ---------------- SpMM: column-half passes for L2 residency ----------------
template<int PHASE, int HALF>
__global__ __launch_bounds__(256)
void spmm_kernel(int n) {
    const float* feat = (PHASE == 0) ? g_t : g_h1;
    int warp = (blockIdx.x * blockDim.x + threadIdx.x) >> 5;
    int lane = threadIdx.x & 31;
    if (warp >= n) return;
    int beg = g_rowptr[warp];
    int end = g_rowptr[warp + 1];
    const float4* f4 = (const float4*)feat;
    const int co = HALF * 32;
    float4 acc0 = make_float4(0.f, 0.f, 0.f, 0.f);
    int e = beg;
    for (; e + 1 < end; e += 2) {
        int   r0 = g_src[e],     r1 = g_src[e + 1];
        float w0 = g_val[e],     w1 = g_val[e + 1];
        float4 a0 = f4[(size_t)r0 * 64 + co + lane];
        float4 a1 = f4[(size_t)r1 * 64 + co + lane];
        acc0.x = fmaf(w0, a0.x, acc0.x); acc0.y = fmaf(w0, a0.y, acc0.y);
        acc0.z = fmaf(w0, a0.z, acc0.z); acc0.w = fmaf(w0, a0.w, acc0.w);
        acc0.x = fmaf(w1, a1.x, acc0.x); acc0.y = fmaf(w1, a1.y, acc0.y);
        acc0.z = fmaf(w1, a1.z, acc0.z); acc0.w = fmaf(w1, a1.w, acc0.w);
    }
    if (e < end) {
        int   r = g_src[e];
        float v = g_val[e];
        float4 a = f4[(size_t)r * 64 + co + lane];
        acc0.x = fmaf(v, a.x, acc0.x); acc0.y = fmaf(v, a.y, acc0.y);
        acc0.z = fmaf(v, a.z, acc0.z); acc0.w = fmaf(v, a.w, acc0.w);
    }
    float di = g_dinv[warp];
    float d2 = di * di;
    float4 s0 = f4[(size_t)warp * 64 + co + lane];
    float4 o0;
    o0.x = di * acc0.x + d2 * s0.x; o0.y = di * acc0.y + d2 * s0.y;
    o0.z = di * acc0.z + d2 * s0.z; o0.w = di * acc0.w + d2 * s0.w;
    if (PHASE == 0) {
        ((float4*)g_h1)[(size_t)warp * 64 + co + lane] = o0;
    } else {
        unsigned h, l;
        size_t base = (size_t)warp * 128 + HALF * 64;
        split_pair(o0.x, o0.y, h, l);
        g_ph[base + 2 * lane] = h;     g_pl[base + 2 * lane] = l;
        split_pair(o0.z, o0.w, h, l);
        g_ph[base + 2 * lane + 1] = h; g_pl[base + 2 * lane + 1] = l;
    }
}

// ---------------- launch ----------------
extern "C" void kernel_launch(void* const* d_in, const int* in_sizes, int n_in,
                              void* d_out, int out_size) {
    const float* x  = (const float*)d_in[0];
    const void*  ei = d_in[1];
    const float* ew = (const float*)d_in[2];
    const float* wd = (const float*)d_in[3];
    const float* bd = (const float*)d_in[4];
    const float* we = (const float*)d_in[5];
    const float* be = (const float*)d_in[6];
    const float* wm = (const float*)d_in[7];
    const float* bmu = (const float*)d_in[8];
    const float* wl = (const float*)d_in[9];
    const float* bl = (const float*)d_in[10];
    float* out = (float*)d_out;

    const int n = NN;
    const int e = EE;

    dim3 grid(2, (n + 127) / 128);
    int spmm_blocks = (n * 32 + 255) / 256;

    // fork/join: prep chain (CSR build + weight composition) runs concurrently
    // with the split_x -> split_wd -> gemm0 path.
    cudaStream_t s2;
    cudaStreamCreateWithFlags(&s2, cudaStreamNonBlocking);
    cudaEvent_t evFork, evJoin;
    cudaEventCreateWithFlags(&evFork, cudaEventDisableTiming);
    cudaEventCreateWithFlags(&evJoin, cudaEventDisableTiming);

    // shared root: dtype detection (needed by edge_pass/scatter on s2)
    detect_kernel<<<1, 1024>>>((const int*)ei, 2 * e);
    cudaEventRecord(evFork, 0);
    cudaStreamWaitEvent(s2, evFork, 0);

    // --- branch s2: graph prep + composed weights ---
    w2_kernel<<<256, 256, 0, s2>>>(we, wm, wl);
    bvec_kernel<<<1, 256, 0, s2>>>(be, wm, wl, bmu, bl);
    split_w2_kernel<<<128, 256, 0, s2>>>();
    init_kernel<<<(n + 255) / 256, 256, 0, s2>>>(n);
    edge_pass<<<(e + 255) / 256, 256, 0, s2>>>(ei, ew, e);
    dinv_kernel<<<(n + 255) / 256, 256, 0, s2>>>(n);
    scan_kernel<<<1, 1024, 0, s2>>>(n);
    scatter_kernel<<<(e + 255) / 256, 256, 0, s2>>>(ei, ew, e);
    rowsum_kernel<<<(n + 255) / 256, 256, 0, s2>>>(n);
    cudaEventRecord(evJoin, s2);

    // --- main branch: split + gemm0 ---
    split_x_kernel<<<(NN * 64 + 255) / 256, 256>>>(x);
    split_wd_kernel<<<128, 256>>>(wd);
    gemm_tc<0><<<grid, 256>>>(bd, nullptr, n);     // h0 -> g_t

    // join: SpMMs need both g_t (main) and CSR/rowsum (s2)
    cudaStreamWaitEvent(0, evJoin, 0);

    spmm_kernel<0, 0><<<spmm_blocks, 256>>>(n);
    spmm_kernel<0, 1><<<spmm_blocks, 256>>>(n);
    spmm_kernel<1, 0><<<spmm_blocks, 256>>>(n);
    spmm_kernel<1, 1><<<spmm_blocks, 256>>>(n);
    gemm_tc<2><<<grid, 256>>>(nullptr, out, n);    // mu/logstd
}